// round 8
// baseline (speedup 1.0000x reference)
#include <cuda_runtime.h>
#include <cuda_fp16.h>
#include <math.h>
#include <stdint.h>

#define B_  4
#define L_  2048
#define D_  512
#define H_  8
#define DH_ 64
#define NTOK (B_ * L_)   // 8192

// Scratch (allocation-free rule: __device__ globals).
__device__ __half g_q[(size_t)B_ * H_ * L_ * DH_];
__device__ __half g_k[(size_t)B_ * H_ * L_ * DH_];
__device__ __half g_v[(size_t)B_ * H_ * L_ * DH_];
__device__ __half g_e[(size_t)L_ * DH_];
__device__ __half g_oh[(size_t)B_ * H_ * L_ * DH_];

// ===========================================================================
// helpers
// ===========================================================================
__device__ __forceinline__ uint32_t smem_u32(const void* p) {
    uint32_t a;
    asm("{ .reg .u64 t; cvta.to.shared.u64 t, %1; cvt.u32.u64 %0, t; }"
        : "=r"(a) : "l"(p));
    return a;
}

__device__ __forceinline__ uint32_t pack2h(float x, float y) {
    __half2 h = __floats2half2_rn(x, y);
    return *reinterpret_cast<uint32_t*>(&h);
}

__device__ __forceinline__ float fex2(float x) {
    float r;
    asm("ex2.approx.f32 %0, %1;" : "=f"(r) : "f"(x));
    return r;
}

__device__ __forceinline__ void mma_f16(float c[4], const uint32_t a[4],
                                        uint32_t b0, uint32_t b1) {
    asm volatile(
        "mma.sync.aligned.m16n8k16.row.col.f32.f16.f16.f32 "
        "{%0,%1,%2,%3}, {%4,%5,%6,%7}, {%8,%9}, {%0,%1,%2,%3};"
        : "+f"(c[0]), "+f"(c[1]), "+f"(c[2]), "+f"(c[3])
        : "r"(a[0]), "r"(a[1]), "r"(a[2]), "r"(a[3]), "r"(b0), "r"(b1));
}

__device__ __forceinline__ void ldsm4(uint32_t r[4], uint32_t addr) {
    asm volatile("ldmatrix.sync.aligned.m8n8.x4.shared.b16 {%0,%1,%2,%3}, [%4];"
                 : "=r"(r[0]), "=r"(r[1]), "=r"(r[2]), "=r"(r[3]) : "r"(addr));
}
__device__ __forceinline__ void ldsm4t(uint32_t r[4], uint32_t addr) {
    asm volatile("ldmatrix.sync.aligned.m8n8.x4.trans.shared.b16 {%0,%1,%2,%3}, [%4];"
                 : "=r"(r[0]), "=r"(r[1]), "=r"(r[2]), "=r"(r[3]) : "r"(addr));
}

// ---------------------------------------------------------------------------
// E fp16 prep
// ---------------------------------------------------------------------------
__global__ void eprep_kernel(const float* __restrict__ E) {
    int i = blockIdx.x * 256 + threadIdx.x;
    if (i < L_ * DH_) g_e[i] = __float2half_rn(E[i]);
}

// ===========================================================================
// MMA GEMM machinery (128x128 CTA tile, 256 threads, 8 warps 4x2,
// warp tile 32x64, K chunk 32, 2-stage smem double buffer, plain fp16).
// JIT loads (no register staging) + 2 CTAs/SM for latency cover.
// smem stage: A @0 (10240 B), B @10240. Stage 20480, total 40960.
// ===========================================================================
#define GSTRIDE 80
#define PANEL   10240
#define STAGE   20480
#define GEMM_SMEM (2 * STAGE)
#define KCH 16

__device__ __forceinline__ void cvt_sts(char* smc, uint32_t off, float4 v) {
    *(uint2*)(smc + off) = make_uint2(pack2h(v.x, v.y), pack2h(v.z, v.w));
}

// one 32-K chunk of fp16 MMAs for this warp
__device__ __forceinline__ void gemm_chunk(uint32_t stg, int warp_m, int warp_n,
                                           int ln, float acc[2][8][4])
{
    const uint32_t aoff = (uint32_t)((ln & 15) * GSTRIDE + (ln >> 4) * 16);
    const uint32_t boff = (uint32_t)(((ln & 7) + ((ln >> 4) << 3)) * GSTRIDE
                                     + (((ln >> 3) & 1) << 4));
    #pragma unroll
    for (int ks = 0; ks < 2; ks++) {
        uint32_t ah[2][4];
        #pragma unroll
        for (int mb = 0; mb < 2; mb++)
            ldsm4(ah[mb], stg + (uint32_t)((warp_m * 32 + mb * 16) * GSTRIDE + ks * 32) + aoff);
        #pragma unroll
        for (int nb = 0; nb < 4; nb++) {
            uint32_t bh_[4];
            ldsm4(bh_, stg + PANEL
                       + (uint32_t)((warp_n * 64 + nb * 16) * GSTRIDE + ks * 32) + boff);
            #pragma unroll
            for (int mb = 0; mb < 2; mb++) {
                mma_f16(acc[mb][2 * nb],     ah[mb], bh_[0], bh_[1]);
                mma_f16(acc[mb][2 * nb + 1], ah[mb], bh_[2], bh_[3]);
            }
        }
    }
}

// ---------------------------------------------------------------------------
// QKV projection on tensor cores -> fp16 head layout.
// ---------------------------------------------------------------------------
__global__ __launch_bounds__(256, 2) void proj_mma_kernel(
    const float* __restrict__ Xq, const float* __restrict__ Xk, const float* __restrict__ Xv,
    const float* __restrict__ Wq, const float* __restrict__ Wk, const float* __restrict__ Wv,
    const float* __restrict__ bq, const float* __restrict__ bk, const float* __restrict__ bv)
{
    extern __shared__ char smc[];
    const uint32_t sbase = smem_u32(smc);

    const float *X, *W, *bias;
    __half* Y;
    if (blockIdx.z == 0)      { X = Xq; W = Wq; bias = bq; Y = g_q; }
    else if (blockIdx.z == 1) { X = Xk; W = Wk; bias = bk; Y = g_k; }
    else                      { X = Xv; W = Wv; bias = bv; Y = g_v; }

    const int t   = threadIdx.x;
    const int wid = t >> 5;
    const int ln  = t & 31;
    const int warp_m = wid >> 1;
    const int warp_n = wid & 1;
    const int m0 = blockIdx.x * 128;
    const int n0 = blockIdx.y * 128;

    // JIT loader for one chunk into one stage (no register staging)
    auto loadsts = [&](int k0, uint32_t so) {
        #pragma unroll
        for (int r = 0; r < 4; r++) {
            int idx = t + r * 256;
            int row = idx >> 3;
            int cg  = idx & 7;
            uint32_t o = so + (uint32_t)(row * GSTRIDE + cg * 8);
            cvt_sts(smc, o,         *(const float4*)(X + (size_t)(m0 + row) * D_ + k0 + cg * 4));
            cvt_sts(smc, o + PANEL, *(const float4*)(W + (size_t)(n0 + row) * D_ + k0 + cg * 4));
        }
    };

    float acc[2][8][4] = {};

    loadsts(0, 0);
    __syncthreads();

    for (int p = 0; p < KCH; p++) {
        const int s = p & 1;
        gemm_chunk(sbase + (uint32_t)s * STAGE, warp_m, warp_n, ln, acc);
        if (p < KCH - 1) loadsts((p + 1) * 32, (uint32_t)(s ^ 1) * STAGE);
        __syncthreads();
    }

    const int g  = ln >> 2;
    const int tq = ln & 3;
    #pragma unroll
    for (int mb = 0; mb < 2; mb++) {
        int r0 = m0 + warp_m * 32 + mb * 16 + g;
        int r1 = r0 + 8;
        int bb0 = r0 >> 11, ll0 = r0 & (L_ - 1);
        int bb1 = r1 >> 11, ll1 = r1 & (L_ - 1);
        #pragma unroll
        for (int f = 0; f < 8; f++) {
            int col = n0 + warp_n * 64 + f * 8 + 2 * tq;
            int hh = col >> 6, dh = col & 63;
            float b0 = bias[col], b1 = bias[col + 1];
            size_t o0 = (((size_t)bb0 * H_ + hh) * L_ + ll0) * DH_ + dh;
            *(uint32_t*)(Y + o0) = pack2h(acc[mb][f][0] + b0, acc[mb][f][1] + b1);
            size_t o1 = (((size_t)bb1 * H_ + hh) * L_ + ll1) * DH_ + dh;
            *(uint32_t*)(Y + o1) = pack2h(acc[mb][f][2] + b0, acc[mb][f][3] + b1);
        }
    }
}

// ---------------------------------------------------------------------------
// Output projection: gathers fp16 (B,H,L,DH) rows from g_oh -> fp32 out.
// ---------------------------------------------------------------------------
__global__ __launch_bounds__(256, 2) void fc_mma_kernel(
    const float* __restrict__ Wf, const float* __restrict__ bf, float* __restrict__ out)
{
    extern __shared__ char smc[];
    const uint32_t sbase = smem_u32(smc);

    const int t   = threadIdx.x;
    const int wid = t >> 5;
    const int ln  = t & 31;
    const int warp_m = wid >> 1;
    const int warp_n = wid & 1;
    const int m0 = blockIdx.x * 128;
    const int n0 = blockIdx.y * 128;

    auto loadsts = [&](int k0, uint32_t so) {
        #pragma unroll
        for (int r = 0; r < 4; r++) {
            int idx = t + r * 256;
            int row = idx >> 3;
            int cg  = idx & 7;
            int n   = m0 + row;
            int bb  = n >> 11, ll = n & (L_ - 1);
            int d   = k0 + cg * 4;
            int hh  = d >> 6, dh = d & 63;
            uint32_t o = so + (uint32_t)(row * GSTRIDE + cg * 8);
            *(uint2*)(smc + o) =
                *(const uint2*)(g_oh + (((size_t)bb * H_ + hh) * L_ + ll) * DH_ + dh);
            cvt_sts(smc, o + PANEL,
                    *(const float4*)(Wf + (size_t)(n0 + row) * D_ + k0 + cg * 4));
        }
    };

    float acc[2][8][4] = {};

    loadsts(0, 0);
    __syncthreads();

    for (int p = 0; p < KCH; p++) {
        const int s = p & 1;
        gemm_chunk(sbase + (uint32_t)s * STAGE, warp_m, warp_n, ln, acc);
        if (p < KCH - 1) loadsts((p + 1) * 32, (uint32_t)(s ^ 1) * STAGE);
        __syncthreads();
    }

    const int g  = ln >> 2;
    const int tq = ln & 3;
    #pragma unroll
    for (int mb = 0; mb < 2; mb++) {
        int r0 = m0 + warp_m * 32 + mb * 16 + g;
        int r1 = r0 + 8;
        #pragma unroll
        for (int f = 0; f < 8; f++) {
            int col = n0 + warp_n * 64 + f * 8 + 2 * tq;
            float b0 = bf[col], b1 = bf[col + 1];
            *(float2*)(out + (size_t)r0 * D_ + col) =
                make_float2(acc[mb][f][0] + b0, acc[mb][f][1] + b1);
            *(float2*)(out + (size_t)r1 * D_ + col) =
                make_float2(acc[mb][f][2] + b0, acc[mb][f][3] + b1);
        }
    }
}

// ===========================================================================
// Attention: flash-style causal + rel-pos, plain fp16 mma.sync,
// double-buffered pipelined tile loads (3 syncs per key tile).
// 128 threads (4 warps); warp w owns q rows [w*16, w*16+16).
// smem: PanA fp32 64x68 @0 (Q fp16 aliases in prologue) | PanB @17408 |
//       WK0 @34816 | WK1 @44032.  Total 53248 B.
// ===========================================================================
#define PAN_A   0
#define PAN_B   17408
#define QH_OFF  0
#define WK0     34816
#define WK1     44032
#define ATTN_SMEM 53248
#define TSTRIDE 144   // bytes per smem tile row (72 fp16)
#define SCL 0.18033688011112042f   // 0.125 * log2(e)

__device__ __forceinline__ void load_tile(char* smc, int woff,
    const __half* __restrict__ src, int rowbase, int t, int clampE)
{
    #pragma unroll
    for (int r = 0; r < 4; r++) {
        int idx = t + r * 128;
        int row = idx >> 3, c8 = idx & 7;
        int gr = rowbase + row;
        if (clampE) gr = (gr < L_) ? gr : (L_ - 1);
        *(uint4*)(smc + woff + row * TSTRIDE + c8 * 16) =
            *(const uint4*)(src + (size_t)gr * DH_ + c8 * 8);
    }
}

// acc[8][4] = Qwarp(16 x 64) * tile(64 x 64)^T, plain fp16
__device__ __forceinline__ void gemm_tile(float acc[8][4],
    const uint32_t qf[4][4], uint32_t th, uint32_t boff)
{
    #pragma unroll
    for (int f = 0; f < 8; f++)
        #pragma unroll
        for (int c = 0; c < 4; c++) acc[f][c] = 0.f;
    #pragma unroll
    for (int kc = 0; kc < 4; kc++) {
        #pragma unroll
        for (int nbp = 0; nbp < 4; nbp++) {
            uint32_t bh_[4];
            ldsm4(bh_, th + (uint32_t)(nbp * 16 * TSTRIDE + kc * 32) + boff);
            mma_f16(acc[2 * nbp],     qf[kc], bh_[0], bh_[1]);
            mma_f16(acc[2 * nbp + 1], qf[kc], bh_[2], bh_[3]);
        }
    }
}

__device__ __forceinline__ void store_panel(float* pan, const float acc[8][4],
                                            int prow, int tq)
{
    #pragma unroll
    for (int f = 0; f < 8; f++) {
        *(float2*)&pan[prow * 68 + 8 * f + 2 * tq]       = make_float2(acc[f][0], acc[f][1]);
        *(float2*)&pan[(prow + 8) * 68 + 8 * f + 2 * tq] = make_float2(acc[f][2], acc[f][3]);
    }
}

__global__ __launch_bounds__(128) void attn_kernel()
{
    extern __shared__ char smc[];
    const uint32_t sbase = smem_u32(smc);
    float* PanAp = (float*)(smc + PAN_A);
    float* PanBp = (float*)(smc + PAN_B);

    const int t  = threadIdx.x;
    const int w  = t >> 5;
    const int ln = t & 31;
    const int g  = ln >> 2;
    const int tq = ln & 3;
    const int qt = (int)(gridDim.x - 1) - (int)blockIdx.x;  // heavy first
    const int l0 = qt * 64;
    const int bh = blockIdx.y;

    const size_t hoff = (size_t)bh * L_ * DH_;

    const uint32_t aoff = (uint32_t)((w * 16 + (ln & 15)) * TSTRIDE + (ln >> 4) * 16);
    const uint32_t boff = (uint32_t)(((ln & 7) + ((ln >> 4) << 3)) * TSTRIDE + (((ln >> 3) & 1) << 4));
    const uint32_t voff = (uint32_t)(((ln & 7) + (((ln >> 3) & 1) << 3)) * TSTRIDE + ((ln >> 4) << 4));

    // prologue: Q tile (aliases panel space), E(jb) tile into WK0
    load_tile(smc, QH_OFF, g_q + hoff, l0, t, 0);
    const int jb = L_ - 64 - l0;
    load_tile(smc, WK0, g_e, jb, t, 0);
    __syncthreads();

    uint32_t qf[4][4];
    #pragma unroll
    for (int kc = 0; kc < 4; kc++)
        ldsm4(qf[kc], sbase + QH_OFF + kc * 32 + aoff);
    __syncthreads();   // Q smem dead; panels writable

    int wo_c = WK0, wo_n = WK1;   // compute-buffer / next-buffer offsets

    float acc[8][4];

    // step 0: prefetch E(jb+64) -> WK1; compute prologue QE panel -> PanA
    load_tile(smc, wo_n, g_e, jb + 64, t, 1);
    gemm_tile(acc, qf, sbase + (uint32_t)wo_c, boff);
    store_panel(PanAp, acc, w * 16 + g, tq);
    __syncthreads();
    { int tmp = wo_c; wo_c = wo_n; wo_n = tmp; }

    float* plo = PanAp;
    float* phi = PanBp;

    float Oa[8][4] = {};
    float rm0 = -1e30f, rm1 = -1e30f, rl0 = 0.f, rl1 = 0.f;

    const int rt0 = w * 16 + g;
    const int rt1 = rt0 + 8;
    const int ntiles = qt + 1;

    for (int tt = 0; tt < ntiles; tt++) {
        const int m0k = tt * 64;

        // --- QE step: prefetch K(tt); compute QE panel -> phi ---
        load_tile(smc, wo_n, g_k + hoff, m0k, t, 0);
        gemm_tile(acc, qf, sbase + (uint32_t)wo_c, boff);
        store_panel(phi, acc, rt0, tq);
        __syncthreads();
        { int tmp = wo_c; wo_c = wo_n; wo_n = tmp; }

        // --- S step: prefetch V(tt); compute S; gather+mask; softmax ---
        load_tile(smc, wo_n, g_v + hoff, m0k, t, 0);
        gemm_tile(acc, qf, sbase + (uint32_t)wo_c, boff);

        #pragma unroll
        for (int f = 0; f < 8; f++) {
            int mi = 8 * f + 2 * tq;
            #pragma unroll
            for (int c = 0; c < 2; c++) {
                int cc = 63 - rt0 + mi + c;
                float rel = (cc < 64) ? plo[rt0 * 68 + cc] : phi[rt0 * 68 + cc - 64];
                float sv  = (acc[f][c] + rel) * SCL;
                acc[f][c] = (m0k + mi + c <= l0 + rt0) ? sv : -1e30f;
            }
            #pragma unroll
            for (int c = 0; c < 2; c++) {
                int cc = 63 - rt1 + mi + c;
                float rel = (cc < 64) ? plo[rt1 * 68 + cc] : phi[rt1 * 68 + cc - 64];
                float sv  = (acc[f][2 + c] + rel) * SCL;
                acc[f][2 + c] = (m0k + mi + c <= l0 + rt1) ? sv : -1e30f;
            }
        }

        // online softmax in log2 domain (overlaps V load latency)
        float mx0 = -1e30f, mx1 = -1e30f;
        #pragma unroll
        for (int f = 0; f < 8; f++) {
            mx0 = fmaxf(mx0, fmaxf(acc[f][0], acc[f][1]));
            mx1 = fmaxf(mx1, fmaxf(acc[f][2], acc[f][3]));
        }
        mx0 = fmaxf(mx0, __shfl_xor_sync(0xffffffffu, mx0, 1));
        mx0 = fmaxf(mx0, __shfl_xor_sync(0xffffffffu, mx0, 2));
        mx1 = fmaxf(mx1, __shfl_xor_sync(0xffffffffu, mx1, 1));
        mx1 = fmaxf(mx1, __shfl_xor_sync(0xffffffffu, mx1, 2));
        float mn0 = fmaxf(rm0, mx0), mn1 = fmaxf(rm1, mx1);
        float cr0 = fex2(rm0 - mn0), cr1 = fex2(rm1 - mn1);
        float s0 = 0.f, s1 = 0.f;
        #pragma unroll
        for (int f = 0; f < 8; f++) {
            acc[f][0] = fex2(acc[f][0] - mn0); s0 += acc[f][0];
            acc[f][1] = fex2(acc[f][1] - mn0); s0 += acc[f][1];
            acc[f][2] = fex2(acc[f][2] - mn1); s1 += acc[f][2];
            acc[f][3] = fex2(acc[f][3] - mn1); s1 += acc[f][3];
        }
        s0 += __shfl_xor_sync(0xffffffffu, s0, 1);
        s0 += __shfl_xor_sync(0xffffffffu, s0, 2);
        s1 += __shfl_xor_sync(0xffffffffu, s1, 1);
        s1 += __shfl_xor_sync(0xffffffffu, s1, 2);
        rl0 = rl0 * cr0 + s0; rm0 = mn0;
        rl1 = rl1 * cr1 + s1; rm1 = mn1;
        #pragma unroll
        for (int f = 0; f < 8; f++) {
            Oa[f][0] *= cr0; Oa[f][1] *= cr0;
            Oa[f][2] *= cr1; Oa[f][3] *= cr1;
        }
        __syncthreads();
        { int tmp = wo_c; wo_c = wo_n; wo_n = tmp; }

        // --- PV step: prefetch E for next tile; O += P @ V ---
        if (tt + 1 < ntiles)
            load_tile(smc, wo_n, g_e, jb + 64 * (tt + 2), t, 1);

        #pragma unroll
        for (int kc = 0; kc < 4; kc++) {
            uint32_t pha[4];
            pha[0] = pack2h(acc[2 * kc][0],     acc[2 * kc][1]);
            pha[1] = pack2h(acc[2 * kc][2],     acc[2 * kc][3]);
            pha[2] = pack2h(acc[2 * kc + 1][0], acc[2 * kc + 1][1]);
            pha[3] = pack2h(acc[2 * kc + 1][2], acc[2 * kc + 1][3]);
            #pragma unroll
            for (int nb = 0; nb < 4; nb++) {
                uint32_t vh_[4];
                ldsm4t(vh_, sbase + (uint32_t)wo_c
                             + (uint32_t)(kc * 16 * TSTRIDE + nb * 32) + voff);
                mma_f16(Oa[2 * nb],     pha, vh_[0], vh_[1]);
                mma_f16(Oa[2 * nb + 1], pha, vh_[2], vh_[3]);
            }
        }
        __syncthreads();
        { int tmp = wo_c; wo_c = wo_n; wo_n = tmp; }

        float* tmp = plo; plo = phi; phi = tmp;
    }

    // epilogue: fp16 output (fc rounds to fp16 anyway)
    float inv0 = 1.0f / rl0, inv1 = 1.0f / rl1;
    __half* op = g_oh + hoff;
    #pragma unroll
    for (int f = 0; f < 8; f++) {
        int col = 8 * f + 2 * tq;
        *(uint32_t*)(op + (size_t)(l0 + rt0) * DH_ + col) =
            pack2h(Oa[f][0] * inv0, Oa[f][1] * inv0);
        *(uint32_t*)(op + (size_t)(l0 + rt1) * DH_ + col) =
            pack2h(Oa[f][2] * inv1, Oa[f][3] * inv1);
    }
}

// ---------------------------------------------------------------------------
extern "C" void kernel_launch(void* const* d_in, const int* in_sizes, int n_in,
                              void* d_out, int out_size)
{
    const float* Q  = (const float*)d_in[0];
    const float* K  = (const float*)d_in[1];
    const float* V  = (const float*)d_in[2];
    // d_in[3] = mask (causal, known analytically) - unused
    const float* Wq = (const float*)d_in[4];
    const float* bq = (const float*)d_in[5];
    const float* Wk = (const float*)d_in[6];
    const float* bk = (const float*)d_in[7];
    const float* Wv = (const float*)d_in[8];
    const float* bv = (const float*)d_in[9];
    const float* Wf = (const float*)d_in[10];
    const float* bf = (const float*)d_in[11];
    const float* E  = (const float*)d_in[12];
    // d_in[13] = H (known constant 8) - unused
    float* out = (float*)d_out;

    (void)in_sizes; (void)n_in; (void)out_size;

    eprep_kernel<<<(L_ * DH_ + 255) / 256, 256>>>(E);

    cudaFuncSetAttribute(proj_mma_kernel, cudaFuncAttributeMaxDynamicSharedMemorySize,
                         GEMM_SMEM);
    cudaFuncSetAttribute(fc_mma_kernel, cudaFuncAttributeMaxDynamicSharedMemorySize,
                         GEMM_SMEM);
    cudaFuncSetAttribute(attn_kernel, cudaFuncAttributeMaxDynamicSharedMemorySize,
                         ATTN_SMEM);

    dim3 gproj(NTOK / 128, D_ / 128, 3);
    proj_mma_kernel<<<gproj, 256, GEMM_SMEM>>>(Q, K, V, Wq, Wk, Wv, bq, bk, bv);

    dim3 gattn(L_ / 64, B_ * H_);
    attn_kernel<<<gattn, 128, ATTN_SMEM>>>();

    dim3 gfc(NTOK / 128, D_ / 128);
    fc_mma_kernel<<<gfc, 256, GEMM_SMEM>>>(Wf, bf, out);
}

// round 9
// speedup vs baseline: 1.0090x; 1.0090x over previous
#include <cuda_runtime.h>
#include <cuda_fp16.h>
#include <math.h>
#include <stdint.h>

#define B_  4
#define L_  2048
#define D_  512
#define H_  8
#define DH_ 64
#define NTOK (B_ * L_)   // 8192

// Scratch (allocation-free rule: __device__ globals).
__device__ __half g_q[(size_t)B_ * H_ * L_ * DH_];
__device__ __half g_k[(size_t)B_ * H_ * L_ * DH_];
__device__ __half g_v[(size_t)B_ * H_ * L_ * DH_];
__device__ __half g_e[(size_t)L_ * DH_];
__device__ __half g_oh[(size_t)B_ * H_ * L_ * DH_];

// ===========================================================================
// helpers
// ===========================================================================
__device__ __forceinline__ uint32_t smem_u32(const void* p) {
    uint32_t a;
    asm("{ .reg .u64 t; cvta.to.shared.u64 t, %1; cvt.u32.u64 %0, t; }"
        : "=r"(a) : "l"(p));
    return a;
}

__device__ __forceinline__ uint32_t pack2h(float x, float y) {
    __half2 h = __floats2half2_rn(x, y);
    return *reinterpret_cast<uint32_t*>(&h);
}

__device__ __forceinline__ float fex2(float x) {
    float r;
    asm("ex2.approx.f32 %0, %1;" : "=f"(r) : "f"(x));
    return r;
}

__device__ __forceinline__ void mma_f16(float c[4], const uint32_t a[4],
                                        uint32_t b0, uint32_t b1) {
    asm volatile(
        "mma.sync.aligned.m16n8k16.row.col.f32.f16.f16.f32 "
        "{%0,%1,%2,%3}, {%4,%5,%6,%7}, {%8,%9}, {%0,%1,%2,%3};"
        : "+f"(c[0]), "+f"(c[1]), "+f"(c[2]), "+f"(c[3])
        : "r"(a[0]), "r"(a[1]), "r"(a[2]), "r"(a[3]), "r"(b0), "r"(b1));
}

__device__ __forceinline__ void ldsm4(uint32_t r[4], uint32_t addr) {
    asm volatile("ldmatrix.sync.aligned.m8n8.x4.shared.b16 {%0,%1,%2,%3}, [%4];"
                 : "=r"(r[0]), "=r"(r[1]), "=r"(r[2]), "=r"(r[3]) : "r"(addr));
}
__device__ __forceinline__ void ldsm4t(uint32_t r[4], uint32_t addr) {
    asm volatile("ldmatrix.sync.aligned.m8n8.x4.trans.shared.b16 {%0,%1,%2,%3}, [%4];"
                 : "=r"(r[0]), "=r"(r[1]), "=r"(r[2]), "=r"(r[3]) : "r"(addr));
}

// ---------------------------------------------------------------------------
// E fp16 prep
// ---------------------------------------------------------------------------
__global__ void eprep_kernel(const float* __restrict__ E) {
    int i = blockIdx.x * 256 + threadIdx.x;
    if (i < L_ * DH_) g_e[i] = __float2half_rn(E[i]);
}

// ===========================================================================
// MMA GEMM machinery (128x128 CTA tile, 256 threads, 8 warps 4x2,
// warp tile 32x64, K chunk 64, 2-stage smem double buffer, plain fp16).
// smem stage: A @0 (18432 B), B @18432. Stage 36864, total 73728.
// ===========================================================================
#define GSTRIDE 144
#define PANEL   18432
#define STAGE   36864
#define GEMM_SMEM (2 * STAGE)
#define KCH 8

__device__ __forceinline__ void cvt_sts(char* smc, uint32_t off, float4 v) {
    *(uint2*)(smc + off) = make_uint2(pack2h(v.x, v.y), pack2h(v.z, v.w));
}

// one 64-K chunk of fp16 MMAs for this warp
__device__ __forceinline__ void gemm_chunk(uint32_t stg, int warp_m, int warp_n,
                                           int ln, float acc[2][8][4])
{
    const uint32_t aoff = (uint32_t)((ln & 15) * GSTRIDE + (ln >> 4) * 16);
    const uint32_t boff = (uint32_t)(((ln & 7) + ((ln >> 4) << 3)) * GSTRIDE
                                     + (((ln >> 3) & 1) << 4));
    #pragma unroll
    for (int ks = 0; ks < 4; ks++) {
        uint32_t ah[2][4];
        #pragma unroll
        for (int mb = 0; mb < 2; mb++)
            ldsm4(ah[mb], stg + (uint32_t)((warp_m * 32 + mb * 16) * GSTRIDE + ks * 32) + aoff);
        #pragma unroll
        for (int nb = 0; nb < 4; nb++) {
            uint32_t bh_[4];
            ldsm4(bh_, stg + PANEL
                       + (uint32_t)((warp_n * 64 + nb * 16) * GSTRIDE + ks * 32) + boff);
            #pragma unroll
            for (int mb = 0; mb < 2; mb++) {
                mma_f16(acc[mb][2 * nb],     ah[mb], bh_[0], bh_[1]);
                mma_f16(acc[mb][2 * nb + 1], ah[mb], bh_[2], bh_[3]);
            }
        }
    }
}

// ---------------------------------------------------------------------------
// QKV projection on tensor cores -> fp16 head layout.
// ---------------------------------------------------------------------------
__global__ __launch_bounds__(256, 2) void proj_mma_kernel(
    const float* __restrict__ Xq, const float* __restrict__ Xk, const float* __restrict__ Xv,
    const float* __restrict__ Wq, const float* __restrict__ Wk, const float* __restrict__ Wv,
    const float* __restrict__ bq, const float* __restrict__ bk, const float* __restrict__ bv)
{
    extern __shared__ char smc[];
    const uint32_t sbase = smem_u32(smc);

    const float *X, *W, *bias;
    __half* Y;
    if (blockIdx.z == 0)      { X = Xq; W = Wq; bias = bq; Y = g_q; }
    else if (blockIdx.z == 1) { X = Xk; W = Wk; bias = bk; Y = g_k; }
    else                      { X = Xv; W = Wv; bias = bv; Y = g_v; }

    const int t   = threadIdx.x;
    const int wid = t >> 5;
    const int ln  = t & 31;
    const int warp_m = wid >> 1;
    const int warp_n = wid & 1;
    const int m0 = blockIdx.x * 128;
    const int n0 = blockIdx.y * 128;

    // JIT loader for one 64-wide chunk into one stage
    auto loadsts = [&](int k0, uint32_t so) {
        #pragma unroll
        for (int r = 0; r < 8; r++) {
            int idx = t + r * 256;
            int row = idx >> 4;
            int cg  = idx & 15;
            uint32_t o = so + (uint32_t)(row * GSTRIDE + cg * 8);
            cvt_sts(smc, o,         *(const float4*)(X + (size_t)(m0 + row) * D_ + k0 + cg * 4));
            cvt_sts(smc, o + PANEL, *(const float4*)(W + (size_t)(n0 + row) * D_ + k0 + cg * 4));
        }
    };

    float acc[2][8][4] = {};

    loadsts(0, 0);
    __syncthreads();

    for (int p = 0; p < KCH; p++) {
        const int s = p & 1;
        gemm_chunk(sbase + (uint32_t)s * STAGE, warp_m, warp_n, ln, acc);
        if (p < KCH - 1) loadsts((p + 1) * 64, (uint32_t)(s ^ 1) * STAGE);
        __syncthreads();
    }

    const int g  = ln >> 2;
    const int tq = ln & 3;
    #pragma unroll
    for (int mb = 0; mb < 2; mb++) {
        int r0 = m0 + warp_m * 32 + mb * 16 + g;
        int r1 = r0 + 8;
        int bb0 = r0 >> 11, ll0 = r0 & (L_ - 1);
        int bb1 = r1 >> 11, ll1 = r1 & (L_ - 1);
        #pragma unroll
        for (int f = 0; f < 8; f++) {
            int col = n0 + warp_n * 64 + f * 8 + 2 * tq;
            int hh = col >> 6, dh = col & 63;
            float b0 = bias[col], b1 = bias[col + 1];
            size_t o0 = (((size_t)bb0 * H_ + hh) * L_ + ll0) * DH_ + dh;
            *(uint32_t*)(Y + o0) = pack2h(acc[mb][f][0] + b0, acc[mb][f][1] + b1);
            size_t o1 = (((size_t)bb1 * H_ + hh) * L_ + ll1) * DH_ + dh;
            *(uint32_t*)(Y + o1) = pack2h(acc[mb][f][2] + b0, acc[mb][f][3] + b1);
        }
    }
}

// ---------------------------------------------------------------------------
// Output projection: gathers fp16 (B,H,L,DH) rows from g_oh -> fp32 out.
// ---------------------------------------------------------------------------
__global__ __launch_bounds__(256, 2) void fc_mma_kernel(
    const float* __restrict__ Wf, const float* __restrict__ bf, float* __restrict__ out)
{
    extern __shared__ char smc[];
    const uint32_t sbase = smem_u32(smc);

    const int t   = threadIdx.x;
    const int wid = t >> 5;
    const int ln  = t & 31;
    const int warp_m = wid >> 1;
    const int warp_n = wid & 1;
    const int m0 = blockIdx.x * 128;
    const int n0 = blockIdx.y * 128;

    auto loadsts = [&](int k0, uint32_t so) {
        #pragma unroll
        for (int r = 0; r < 8; r++) {
            int idx = t + r * 256;
            int row = idx >> 4;
            int cg  = idx & 15;
            int n   = m0 + row;
            int bb  = n >> 11, ll = n & (L_ - 1);
            int d   = k0 + cg * 4;
            int hh  = d >> 6, dh = d & 63;
            uint32_t o = so + (uint32_t)(row * GSTRIDE + cg * 8);
            *(uint2*)(smc + o) =
                *(const uint2*)(g_oh + (((size_t)bb * H_ + hh) * L_ + ll) * DH_ + dh);
            cvt_sts(smc, o + PANEL,
                    *(const float4*)(Wf + (size_t)(n0 + row) * D_ + k0 + cg * 4));
        }
    };

    float acc[2][8][4] = {};

    loadsts(0, 0);
    __syncthreads();

    for (int p = 0; p < KCH; p++) {
        const int s = p & 1;
        gemm_chunk(sbase + (uint32_t)s * STAGE, warp_m, warp_n, ln, acc);
        if (p < KCH - 1) loadsts((p + 1) * 64, (uint32_t)(s ^ 1) * STAGE);
        __syncthreads();
    }

    const int g  = ln >> 2;
    const int tq = ln & 3;
    #pragma unroll
    for (int mb = 0; mb < 2; mb++) {
        int r0 = m0 + warp_m * 32 + mb * 16 + g;
        int r1 = r0 + 8;
        #pragma unroll
        for (int f = 0; f < 8; f++) {
            int col = n0 + warp_n * 64 + f * 8 + 2 * tq;
            float b0 = bf[col], b1 = bf[col + 1];
            *(float2*)(out + (size_t)r0 * D_ + col) =
                make_float2(acc[mb][f][0] + b0, acc[mb][f][1] + b1);
            *(float2*)(out + (size_t)r1 * D_ + col) =
                make_float2(acc[mb][f][2] + b0, acc[mb][f][3] + b1);
        }
    }
}

// ===========================================================================
// Attention: flash-style causal + rel-pos, plain fp16 mma.sync,
// double-buffered pipelined tile loads, fp16 QE panels (occupancy!).
// 128 threads (4 warps); warp w owns q rows [w*16, w*16+16).
// smem: PanA fp16 64x68 @0 (8704) | PanB @8704 (8704) |
//       WK0 @17408 (9216) | WK1 @26624 (9216).  Total 35840 B.
//       Q fp16 tile (9216) aliases [0,9216) during prologue only.
// ===========================================================================
#define PAN_A   0
#define PAN_B   8704
#define QH_OFF  0
#define WK0     17408
#define WK1     26624
#define ATTN_SMEM 35840
#define TSTRIDE 144   // bytes per smem tile row (72 fp16)
#define SCL 0.18033688011112042f   // 0.125 * log2(e)

__device__ __forceinline__ void load_tile(char* smc, int woff,
    const __half* __restrict__ src, int rowbase, int t, int clampE)
{
    #pragma unroll
    for (int r = 0; r < 4; r++) {
        int idx = t + r * 128;
        int row = idx >> 3, c8 = idx & 7;
        int gr = rowbase + row;
        if (clampE) gr = (gr < L_) ? gr : (L_ - 1);
        *(uint4*)(smc + woff + row * TSTRIDE + c8 * 16) =
            *(const uint4*)(src + (size_t)gr * DH_ + c8 * 8);
    }
}

// acc[8][4] = Qwarp(16 x 64) * tile(64 x 64)^T, plain fp16
__device__ __forceinline__ void gemm_tile(float acc[8][4],
    const uint32_t qf[4][4], uint32_t th, uint32_t boff)
{
    #pragma unroll
    for (int f = 0; f < 8; f++)
        #pragma unroll
        for (int c = 0; c < 4; c++) acc[f][c] = 0.f;
    #pragma unroll
    for (int kc = 0; kc < 4; kc++) {
        #pragma unroll
        for (int nbp = 0; nbp < 4; nbp++) {
            uint32_t bh_[4];
            ldsm4(bh_, th + (uint32_t)(nbp * 16 * TSTRIDE + kc * 32) + boff);
            mma_f16(acc[2 * nbp],     qf[kc], bh_[0], bh_[1]);
            mma_f16(acc[2 * nbp + 1], qf[kc], bh_[2], bh_[3]);
        }
    }
}

__device__ __forceinline__ void store_panel(__half* pan, const float acc[8][4],
                                            int prow, int tq)
{
    #pragma unroll
    for (int f = 0; f < 8; f++) {
        *(uint32_t*)&pan[prow * 68 + 8 * f + 2 * tq]       = pack2h(acc[f][0], acc[f][1]);
        *(uint32_t*)&pan[(prow + 8) * 68 + 8 * f + 2 * tq] = pack2h(acc[f][2], acc[f][3]);
    }
}

__global__ __launch_bounds__(128, 4) void attn_kernel()
{
    extern __shared__ char smc[];
    const uint32_t sbase = smem_u32(smc);
    __half* PanAp = (__half*)(smc + PAN_A);
    __half* PanBp = (__half*)(smc + PAN_B);

    const int t  = threadIdx.x;
    const int w  = t >> 5;
    const int ln = t & 31;
    const int g  = ln >> 2;
    const int tq = ln & 3;
    const int qt = (int)(gridDim.x - 1) - (int)blockIdx.x;  // heavy first
    const int l0 = qt * 64;
    const int bh = blockIdx.y;

    const size_t hoff = (size_t)bh * L_ * DH_;

    const uint32_t aoff = (uint32_t)((w * 16 + (ln & 15)) * TSTRIDE + (ln >> 4) * 16);
    const uint32_t boff = (uint32_t)(((ln & 7) + ((ln >> 4) << 3)) * TSTRIDE + (((ln >> 3) & 1) << 4));
    const uint32_t voff = (uint32_t)(((ln & 7) + (((ln >> 3) & 1) << 3)) * TSTRIDE + ((ln >> 4) << 4));

    // prologue: Q tile (aliases panel space), E(jb) tile into WK0
    load_tile(smc, QH_OFF, g_q + hoff, l0, t, 0);
    const int jb = L_ - 64 - l0;
    load_tile(smc, WK0, g_e, jb, t, 0);
    __syncthreads();

    uint32_t qf[4][4];
    #pragma unroll
    for (int kc = 0; kc < 4; kc++)
        ldsm4(qf[kc], sbase + QH_OFF + kc * 32 + aoff);
    __syncthreads();   // Q smem dead; panels writable

    int wo_c = WK0, wo_n = WK1;   // compute-buffer / next-buffer offsets

    float acc[8][4];

    // step 0: prefetch E(jb+64) -> WK1; compute prologue QE panel -> PanA
    load_tile(smc, wo_n, g_e, jb + 64, t, 1);
    gemm_tile(acc, qf, sbase + (uint32_t)wo_c, boff);
    store_panel(PanAp, acc, w * 16 + g, tq);
    __syncthreads();
    { int tmp = wo_c; wo_c = wo_n; wo_n = tmp; }

    __half* plo = PanAp;
    __half* phi = PanBp;

    float Oa[8][4] = {};
    float rm0 = -1e30f, rm1 = -1e30f, rl0 = 0.f, rl1 = 0.f;

    const int rt0 = w * 16 + g;
    const int rt1 = rt0 + 8;
    const int ntiles = qt + 1;

    for (int tt = 0; tt < ntiles; tt++) {
        const int m0k = tt * 64;

        // --- QE step: prefetch K(tt); compute QE panel -> phi ---
        load_tile(smc, wo_n, g_k + hoff, m0k, t, 0);
        gemm_tile(acc, qf, sbase + (uint32_t)wo_c, boff);
        store_panel(phi, acc, rt0, tq);
        __syncthreads();
        { int tmp = wo_c; wo_c = wo_n; wo_n = tmp; }

        // --- S step: prefetch V(tt); compute S; gather+mask; softmax ---
        load_tile(smc, wo_n, g_v + hoff, m0k, t, 0);
        gemm_tile(acc, qf, sbase + (uint32_t)wo_c, boff);

        #pragma unroll
        for (int f = 0; f < 8; f++) {
            int mi = 8 * f + 2 * tq;
            #pragma unroll
            for (int c = 0; c < 2; c++) {
                int cc = 63 - rt0 + mi + c;
                float rel = __half2float((cc < 64) ? plo[rt0 * 68 + cc]
                                                   : phi[rt0 * 68 + cc - 64]);
                float sv  = (acc[f][c] + rel) * SCL;
                acc[f][c] = (m0k + mi + c <= l0 + rt0) ? sv : -1e30f;
            }
            #pragma unroll
            for (int c = 0; c < 2; c++) {
                int cc = 63 - rt1 + mi + c;
                float rel = __half2float((cc < 64) ? plo[rt1 * 68 + cc]
                                                   : phi[rt1 * 68 + cc - 64]);
                float sv  = (acc[f][2 + c] + rel) * SCL;
                acc[f][2 + c] = (m0k + mi + c <= l0 + rt1) ? sv : -1e30f;
            }
        }

        // online softmax in log2 domain (overlaps V load latency)
        float mx0 = -1e30f, mx1 = -1e30f;
        #pragma unroll
        for (int f = 0; f < 8; f++) {
            mx0 = fmaxf(mx0, fmaxf(acc[f][0], acc[f][1]));
            mx1 = fmaxf(mx1, fmaxf(acc[f][2], acc[f][3]));
        }
        mx0 = fmaxf(mx0, __shfl_xor_sync(0xffffffffu, mx0, 1));
        mx0 = fmaxf(mx0, __shfl_xor_sync(0xffffffffu, mx0, 2));
        mx1 = fmaxf(mx1, __shfl_xor_sync(0xffffffffu, mx1, 1));
        mx1 = fmaxf(mx1, __shfl_xor_sync(0xffffffffu, mx1, 2));
        float mn0 = fmaxf(rm0, mx0), mn1 = fmaxf(rm1, mx1);
        float cr0 = fex2(rm0 - mn0), cr1 = fex2(rm1 - mn1);
        float s0 = 0.f, s1 = 0.f;
        #pragma unroll
        for (int f = 0; f < 8; f++) {
            acc[f][0] = fex2(acc[f][0] - mn0); s0 += acc[f][0];
            acc[f][1] = fex2(acc[f][1] - mn0); s0 += acc[f][1];
            acc[f][2] = fex2(acc[f][2] - mn1); s1 += acc[f][2];
            acc[f][3] = fex2(acc[f][3] - mn1); s1 += acc[f][3];
        }
        s0 += __shfl_xor_sync(0xffffffffu, s0, 1);
        s0 += __shfl_xor_sync(0xffffffffu, s0, 2);
        s1 += __shfl_xor_sync(0xffffffffu, s1, 1);
        s1 += __shfl_xor_sync(0xffffffffu, s1, 2);
        rl0 = rl0 * cr0 + s0; rm0 = mn0;
        rl1 = rl1 * cr1 + s1; rm1 = mn1;
        #pragma unroll
        for (int f = 0; f < 8; f++) {
            Oa[f][0] *= cr0; Oa[f][1] *= cr0;
            Oa[f][2] *= cr1; Oa[f][3] *= cr1;
        }
        __syncthreads();
        { int tmp = wo_c; wo_c = wo_n; wo_n = tmp; }

        // --- PV step: prefetch E for next tile; O += P @ V ---
        if (tt + 1 < ntiles)
            load_tile(smc, wo_n, g_e, jb + 64 * (tt + 2), t, 1);

        #pragma unroll
        for (int kc = 0; kc < 4; kc++) {
            uint32_t pha[4];
            pha[0] = pack2h(acc[2 * kc][0],     acc[2 * kc][1]);
            pha[1] = pack2h(acc[2 * kc][2],     acc[2 * kc][3]);
            pha[2] = pack2h(acc[2 * kc + 1][0], acc[2 * kc + 1][1]);
            pha[3] = pack2h(acc[2 * kc + 1][2], acc[2 * kc + 1][3]);
            #pragma unroll
            for (int nb = 0; nb < 4; nb++) {
                uint32_t vh_[4];
                ldsm4t(vh_, sbase + (uint32_t)wo_c
                             + (uint32_t)(kc * 16 * TSTRIDE + nb * 32) + voff);
                mma_f16(Oa[2 * nb],     pha, vh_[0], vh_[1]);
                mma_f16(Oa[2 * nb + 1], pha, vh_[2], vh_[3]);
            }
        }
        __syncthreads();
        { int tmp = wo_c; wo_c = wo_n; wo_n = tmp; }

        __half* tmp = plo; plo = phi; phi = tmp;
    }

    // epilogue: fp16 output (fc rounds to fp16 anyway)
    float inv0 = 1.0f / rl0, inv1 = 1.0f / rl1;
    __half* op = g_oh + hoff;
    #pragma unroll
    for (int f = 0; f < 8; f++) {
        int col = 8 * f + 2 * tq;
        *(uint32_t*)(op + (size_t)(l0 + rt0) * DH_ + col) =
            pack2h(Oa[f][0] * inv0, Oa[f][1] * inv0);
        *(uint32_t*)(op + (size_t)(l0 + rt1) * DH_ + col) =
            pack2h(Oa[f][2] * inv1, Oa[f][3] * inv1);
    }
}

// ---------------------------------------------------------------------------
extern "C" void kernel_launch(void* const* d_in, const int* in_sizes, int n_in,
                              void* d_out, int out_size)
{
    const float* Q  = (const float*)d_in[0];
    const float* K  = (const float*)d_in[1];
    const float* V  = (const float*)d_in[2];
    // d_in[3] = mask (causal, known analytically) - unused
    const float* Wq = (const float*)d_in[4];
    const float* bq = (const float*)d_in[5];
    const float* Wk = (const float*)d_in[6];
    const float* bk = (const float*)d_in[7];
    const float* Wv = (const float*)d_in[8];
    const float* bv = (const float*)d_in[9];
    const float* Wf = (const float*)d_in[10];
    const float* bf = (const float*)d_in[11];
    const float* E  = (const float*)d_in[12];
    // d_in[13] = H (known constant 8) - unused
    float* out = (float*)d_out;

    (void)in_sizes; (void)n_in; (void)out_size;

    eprep_kernel<<<(L_ * DH_ + 255) / 256, 256>>>(E);

    cudaFuncSetAttribute(proj_mma_kernel, cudaFuncAttributeMaxDynamicSharedMemorySize,
                         GEMM_SMEM);
    cudaFuncSetAttribute(fc_mma_kernel, cudaFuncAttributeMaxDynamicSharedMemorySize,
                         GEMM_SMEM);
    cudaFuncSetAttribute(attn_kernel, cudaFuncAttributeMaxDynamicSharedMemorySize,
                         ATTN_SMEM);

    dim3 gproj(NTOK / 128, D_ / 128, 3);
    proj_mma_kernel<<<gproj, 256, GEMM_SMEM>>>(Q, K, V, Wq, Wk, Wv, bq, bk, bv);

    dim3 gattn(L_ / 64, B_ * H_);
    attn_kernel<<<gattn, 128, ATTN_SMEM>>>();

    dim3 gfc(NTOK / 128, D_ / 128);
    fc_mma_kernel<<<gfc, 256, GEMM_SMEM>>>(Wf, bf, out);
}

// round 10
// speedup vs baseline: 1.1916x; 1.1809x over previous
#include <cuda_runtime.h>
#include <cuda_fp16.h>
#include <math.h>
#include <stdint.h>

#define B_  4
#define L_  2048
#define D_  512
#define H_  8
#define DH_ 64
#define NTOK (B_ * L_)   // 8192

// Scratch (allocation-free rule: __device__ globals).
__device__ __half g_q[(size_t)B_ * H_ * L_ * DH_];
__device__ __half g_k[(size_t)B_ * H_ * L_ * DH_];
__device__ __half g_v[(size_t)B_ * H_ * L_ * DH_];
__device__ __half g_e[(size_t)L_ * DH_];
__device__ __half g_oh[(size_t)B_ * H_ * L_ * DH_];
__device__ __half g_wq[(size_t)D_ * D_];
__device__ __half g_wk[(size_t)D_ * D_];
__device__ __half g_wv[(size_t)D_ * D_];
__device__ __half g_wf[(size_t)D_ * D_];

// ===========================================================================
// helpers
// ===========================================================================
__device__ __forceinline__ uint32_t smem_u32(const void* p) {
    uint32_t a;
    asm("{ .reg .u64 t; cvta.to.shared.u64 t, %1; cvt.u32.u64 %0, t; }"
        : "=r"(a) : "l"(p));
    return a;
}

__device__ __forceinline__ uint32_t pack2h(float x, float y) {
    __half2 h = __floats2half2_rn(x, y);
    return *reinterpret_cast<uint32_t*>(&h);
}

__device__ __forceinline__ float fex2(float x) {
    float r;
    asm("ex2.approx.f32 %0, %1;" : "=f"(r) : "f"(x));
    return r;
}

// packed half2 2^x
__device__ __forceinline__ uint32_t h2ex2(uint32_t x) {
    uint32_t r;
    asm("ex2.approx.f16x2 %0, %1;" : "=r"(r) : "r"(x));
    return r;
}

__device__ __forceinline__ void mma_f16(float c[4], const uint32_t a[4],
                                        uint32_t b0, uint32_t b1) {
    asm volatile(
        "mma.sync.aligned.m16n8k16.row.col.f32.f16.f16.f32 "
        "{%0,%1,%2,%3}, {%4,%5,%6,%7}, {%8,%9}, {%0,%1,%2,%3};"
        : "+f"(c[0]), "+f"(c[1]), "+f"(c[2]), "+f"(c[3])
        : "r"(a[0]), "r"(a[1]), "r"(a[2]), "r"(a[3]), "r"(b0), "r"(b1));
}

__device__ __forceinline__ void ldsm4(uint32_t r[4], uint32_t addr) {
    asm volatile("ldmatrix.sync.aligned.m8n8.x4.shared.b16 {%0,%1,%2,%3}, [%4];"
                 : "=r"(r[0]), "=r"(r[1]), "=r"(r[2]), "=r"(r[3]) : "r"(addr));
}
__device__ __forceinline__ void ldsm4t(uint32_t r[4], uint32_t addr) {
    asm volatile("ldmatrix.sync.aligned.m8n8.x4.trans.shared.b16 {%0,%1,%2,%3}, [%4];"
                 : "=r"(r[0]), "=r"(r[1]), "=r"(r[2]), "=r"(r[3]) : "r"(addr));
}

// ---------------------------------------------------------------------------
// prep kernels: E -> fp16, weights -> fp16
// ---------------------------------------------------------------------------
__global__ void eprep_kernel(const float* __restrict__ E) {
    int i = blockIdx.x * 256 + threadIdx.x;
    if (i < L_ * DH_) g_e[i] = __float2half_rn(E[i]);
}

__global__ void wprep_kernel(const float* __restrict__ Wq, const float* __restrict__ Wk,
                             const float* __restrict__ Wv, const float* __restrict__ Wf) {
    int i = blockIdx.x * 256 + threadIdx.x;
    if (i < D_ * D_) {
        g_wq[i] = __float2half_rn(Wq[i]);
        g_wk[i] = __float2half_rn(Wk[i]);
        g_wv[i] = __float2half_rn(Wv[i]);
        g_wf[i] = __float2half_rn(Wf[i]);
    }
}

// ===========================================================================
// MMA GEMM machinery (128x128 CTA tile, 256 threads, 8 warps 4x2,
// warp tile 32x64, K chunk 64, 2-stage smem double buffer, plain fp16,
// fp16 weights in gmem).
// smem stage: A @0 (18432 B), B @18432. Stage 36864, total 73728.
// ===========================================================================
#define GSTRIDE 144
#define PANEL   18432
#define STAGE   36864
#define GEMM_SMEM (2 * STAGE)
#define KCH 8

__device__ __forceinline__ void cvt_sts(char* smc, uint32_t off, float4 v) {
    *(uint2*)(smc + off) = make_uint2(pack2h(v.x, v.y), pack2h(v.z, v.w));
}

// one 64-K chunk of fp16 MMAs for this warp
__device__ __forceinline__ void gemm_chunk(uint32_t stg, int warp_m, int warp_n,
                                           int ln, float acc[2][8][4])
{
    const uint32_t aoff = (uint32_t)((ln & 15) * GSTRIDE + (ln >> 4) * 16);
    const uint32_t boff = (uint32_t)(((ln & 7) + ((ln >> 4) << 3)) * GSTRIDE
                                     + (((ln >> 3) & 1) << 4));
    #pragma unroll
    for (int ks = 0; ks < 4; ks++) {
        uint32_t ah[2][4];
        #pragma unroll
        for (int mb = 0; mb < 2; mb++)
            ldsm4(ah[mb], stg + (uint32_t)((warp_m * 32 + mb * 16) * GSTRIDE + ks * 32) + aoff);
        #pragma unroll
        for (int nb = 0; nb < 4; nb++) {
            uint32_t bh_[4];
            ldsm4(bh_, stg + PANEL
                       + (uint32_t)((warp_n * 64 + nb * 16) * GSTRIDE + ks * 32) + boff);
            #pragma unroll
            for (int mb = 0; mb < 2; mb++) {
                mma_f16(acc[mb][2 * nb],     ah[mb], bh_[0], bh_[1]);
                mma_f16(acc[mb][2 * nb + 1], ah[mb], bh_[2], bh_[3]);
            }
        }
    }
}

// ---------------------------------------------------------------------------
// QKV projection on tensor cores -> fp16 head layout.
// ---------------------------------------------------------------------------
__global__ __launch_bounds__(256, 2) void proj_mma_kernel(
    const float* __restrict__ Xq, const float* __restrict__ Xk, const float* __restrict__ Xv,
    const float* __restrict__ bq, const float* __restrict__ bk, const float* __restrict__ bv)
{
    extern __shared__ char smc[];
    const uint32_t sbase = smem_u32(smc);

    const float *X, *bias;
    const __half* Wh;
    __half* Y;
    if (blockIdx.z == 0)      { X = Xq; Wh = g_wq; bias = bq; Y = g_q; }
    else if (blockIdx.z == 1) { X = Xk; Wh = g_wk; bias = bk; Y = g_k; }
    else                      { X = Xv; Wh = g_wv; bias = bv; Y = g_v; }

    const int t   = threadIdx.x;
    const int wid = t >> 5;
    const int ln  = t & 31;
    const int warp_m = wid >> 1;
    const int warp_n = wid & 1;
    const int m0 = blockIdx.x * 128;
    const int n0 = blockIdx.y * 128;

    // JIT loader for one 64-wide chunk into one stage
    auto loadsts = [&](int k0, uint32_t so) {
        #pragma unroll
        for (int r = 0; r < 8; r++) {
            int idx = t + r * 256;
            int row = idx >> 4;
            int cg  = idx & 15;
            uint32_t o = so + (uint32_t)(row * GSTRIDE + cg * 8);
            cvt_sts(smc, o, *(const float4*)(X + (size_t)(m0 + row) * D_ + k0 + cg * 4));
            *(uint2*)(smc + o + PANEL) =
                *(const uint2*)(Wh + (size_t)(n0 + row) * D_ + k0 + cg * 4);
        }
    };

    float acc[2][8][4] = {};

    loadsts(0, 0);
    __syncthreads();

    for (int p = 0; p < KCH; p++) {
        const int s = p & 1;
        gemm_chunk(sbase + (uint32_t)s * STAGE, warp_m, warp_n, ln, acc);
        if (p < KCH - 1) loadsts((p + 1) * 64, (uint32_t)(s ^ 1) * STAGE);
        __syncthreads();
    }

    const int g  = ln >> 2;
    const int tq = ln & 3;
    #pragma unroll
    for (int mb = 0; mb < 2; mb++) {
        int r0 = m0 + warp_m * 32 + mb * 16 + g;
        int r1 = r0 + 8;
        int bb0 = r0 >> 11, ll0 = r0 & (L_ - 1);
        int bb1 = r1 >> 11, ll1 = r1 & (L_ - 1);
        #pragma unroll
        for (int f = 0; f < 8; f++) {
            int col = n0 + warp_n * 64 + f * 8 + 2 * tq;
            int hh = col >> 6, dh = col & 63;
            float b0 = bias[col], b1 = bias[col + 1];
            size_t o0 = (((size_t)bb0 * H_ + hh) * L_ + ll0) * DH_ + dh;
            *(uint32_t*)(Y + o0) = pack2h(acc[mb][f][0] + b0, acc[mb][f][1] + b1);
            size_t o1 = (((size_t)bb1 * H_ + hh) * L_ + ll1) * DH_ + dh;
            *(uint32_t*)(Y + o1) = pack2h(acc[mb][f][2] + b0, acc[mb][f][3] + b1);
        }
    }
}

// ---------------------------------------------------------------------------
// Output projection: gathers fp16 (B,H,L,DH) rows from g_oh -> fp32 out.
// ---------------------------------------------------------------------------
__global__ __launch_bounds__(256, 2) void fc_mma_kernel(
    const float* __restrict__ bf, float* __restrict__ out)
{
    extern __shared__ char smc[];
    const uint32_t sbase = smem_u32(smc);

    const int t   = threadIdx.x;
    const int wid = t >> 5;
    const int ln  = t & 31;
    const int warp_m = wid >> 1;
    const int warp_n = wid & 1;
    const int m0 = blockIdx.x * 128;
    const int n0 = blockIdx.y * 128;

    auto loadsts = [&](int k0, uint32_t so) {
        #pragma unroll
        for (int r = 0; r < 8; r++) {
            int idx = t + r * 256;
            int row = idx >> 4;
            int cg  = idx & 15;
            int n   = m0 + row;
            int bb  = n >> 11, ll = n & (L_ - 1);
            int d   = k0 + cg * 4;
            int hh  = d >> 6, dh = d & 63;
            uint32_t o = so + (uint32_t)(row * GSTRIDE + cg * 8);
            *(uint2*)(smc + o) =
                *(const uint2*)(g_oh + (((size_t)bb * H_ + hh) * L_ + ll) * DH_ + dh);
            *(uint2*)(smc + o + PANEL) =
                *(const uint2*)(g_wf + (size_t)(n0 + row) * D_ + k0 + cg * 4);
        }
    };

    float acc[2][8][4] = {};

    loadsts(0, 0);
    __syncthreads();

    for (int p = 0; p < KCH; p++) {
        const int s = p & 1;
        gemm_chunk(sbase + (uint32_t)s * STAGE, warp_m, warp_n, ln, acc);
        if (p < KCH - 1) loadsts((p + 1) * 64, (uint32_t)(s ^ 1) * STAGE);
        __syncthreads();
    }

    const int g  = ln >> 2;
    const int tq = ln & 3;
    #pragma unroll
    for (int mb = 0; mb < 2; mb++) {
        int r0 = m0 + warp_m * 32 + mb * 16 + g;
        int r1 = r0 + 8;
        #pragma unroll
        for (int f = 0; f < 8; f++) {
            int col = n0 + warp_n * 64 + f * 8 + 2 * tq;
            float b0 = bf[col], b1 = bf[col + 1];
            *(float2*)(out + (size_t)r0 * D_ + col) =
                make_float2(acc[mb][f][0] + b0, acc[mb][f][1] + b1);
            *(float2*)(out + (size_t)r1 * D_ + col) =
                make_float2(acc[mb][f][2] + b0, acc[mb][f][3] + b1);
        }
    }
}

// ===========================================================================
// Attention: flash-style causal + rel-pos, plain fp16 mma.sync,
// double-buffered pipelined tile loads, fp16 QE panel RING (single buffer,
// branch-free gather), f16x2 exp softmax, MMA-based row sums.
// 128 threads (4 warps); warp w owns q rows [w*16, w*16+16).
// smem: Pan fp16 64x136 @0 (17408) | WK0 @17408 (9216) | WK1 @26624 (9216).
//       Total 35840 B.  Q fp16 tile (9216) aliases [0,9216) in prologue only.
// ===========================================================================
#define PAN     0
#define QH_OFF  0
#define WK0     17408
#define WK1     26624
#define ATTN_SMEM 35840
#define TSTRIDE 144   // bytes per smem tile row (72 fp16)
#define PSTRIDE 136   // halves per panel row (128 ring + 8 pad)
#define SCL 0.18033688011112042f   // 0.125 * log2(e)
#define ONESH2 0x3C003C00u         // half2 (1.0, 1.0)

__device__ __forceinline__ void load_tile(char* smc, int woff,
    const __half* __restrict__ src, int rowbase, int t, int clampE)
{
    #pragma unroll
    for (int r = 0; r < 4; r++) {
        int idx = t + r * 128;
        int row = idx >> 3, c8 = idx & 7;
        int gr = rowbase + row;
        if (clampE) gr = (gr < L_) ? gr : (L_ - 1);
        *(uint4*)(smc + woff + row * TSTRIDE + c8 * 16) =
            *(const uint4*)(src + (size_t)gr * DH_ + c8 * 8);
    }
}

// acc[8][4] = Qwarp(16 x 64) * tile(64 x 64)^T, plain fp16
__device__ __forceinline__ void gemm_tile(float acc[8][4],
    const uint32_t qf[4][4], uint32_t th, uint32_t boff)
{
    #pragma unroll
    for (int f = 0; f < 8; f++)
        #pragma unroll
        for (int c = 0; c < 4; c++) acc[f][c] = 0.f;
    #pragma unroll
    for (int kc = 0; kc < 4; kc++) {
        #pragma unroll
        for (int nbp = 0; nbp < 4; nbp++) {
            uint32_t bh_[4];
            ldsm4(bh_, th + (uint32_t)(nbp * 16 * TSTRIDE + kc * 32) + boff);
            mma_f16(acc[2 * nbp],     qf[kc], bh_[0], bh_[1]);
            mma_f16(acc[2 * nbp + 1], qf[kc], bh_[2], bh_[3]);
        }
    }
}

// store one QE panel into ring slot (columns [slot*64, slot*64+64))
__device__ __forceinline__ void store_panel(__half* pan, const float acc[8][4],
                                            int prow, int tq, int slot)
{
    #pragma unroll
    for (int f = 0; f < 8; f++) {
        *(uint32_t*)&pan[prow * PSTRIDE + slot * 64 + 8 * f + 2 * tq] =
            pack2h(acc[f][0], acc[f][1]);
        *(uint32_t*)&pan[(prow + 8) * PSTRIDE + slot * 64 + 8 * f + 2 * tq] =
            pack2h(acc[f][2], acc[f][3]);
    }
}

__global__ __launch_bounds__(128, 4) void attn_kernel()
{
    extern __shared__ char smc[];
    const uint32_t sbase = smem_u32(smc);
    __half* pan = (__half*)(smc + PAN);

    const int t  = threadIdx.x;
    const int w  = t >> 5;
    const int ln = t & 31;
    const int g  = ln >> 2;
    const int tq = ln & 3;
    const int qt = (int)(gridDim.x - 1) - (int)blockIdx.x;  // heavy first
    const int l0 = qt * 64;
    const int bh = blockIdx.y;

    const size_t hoff = (size_t)bh * L_ * DH_;

    const uint32_t aoff = (uint32_t)((w * 16 + (ln & 15)) * TSTRIDE + (ln >> 4) * 16);
    const uint32_t boff = (uint32_t)(((ln & 7) + ((ln >> 4) << 3)) * TSTRIDE + (((ln >> 3) & 1) << 4));
    const uint32_t voff = (uint32_t)(((ln & 7) + (((ln >> 3) & 1) << 3)) * TSTRIDE + ((ln >> 4) << 4));

    // prologue: Q tile (aliases panel space), E(jb) tile into WK0
    load_tile(smc, QH_OFF, g_q + hoff, l0, t, 0);
    const int jb = L_ - 64 - l0;
    load_tile(smc, WK0, g_e, jb, t, 0);
    __syncthreads();

    uint32_t qf[4][4];
    #pragma unroll
    for (int kc = 0; kc < 4; kc++)
        ldsm4(qf[kc], sbase + QH_OFF + kc * 32 + aoff);
    __syncthreads();   // Q smem dead; panel ring writable

    int wo_c = WK0, wo_n = WK1;   // compute-buffer / next-buffer offsets

    float acc[8][4];

    // step 0: prefetch E(jb+64) -> WK1; compute prologue QE panel -> slot 0
    load_tile(smc, wo_n, g_e, jb + 64, t, 1);
    gemm_tile(acc, qf, sbase + (uint32_t)wo_c, boff);
    store_panel(pan, acc, w * 16 + g, tq, 0);
    __syncthreads();
    { int tmp = wo_c; wo_c = wo_n; wo_n = tmp; }

    float Oa[8][4] = {};
    float rm0 = -1e30f, rm1 = -1e30f, rl0 = 0.f, rl1 = 0.f;

    const int rt0 = w * 16 + g;
    const int rt1 = rt0 + 8;
    const int ntiles = qt + 1;

    for (int tt = 0; tt < ntiles; tt++) {
        const int m0k = tt * 64;

        // --- QE step: prefetch K(tt); compute QE panel -> slot (tt+1)&1 ---
        load_tile(smc, wo_n, g_k + hoff, m0k, t, 0);
        gemm_tile(acc, qf, sbase + (uint32_t)wo_c, boff);
        store_panel(pan, acc, rt0, tq, (tt + 1) & 1);
        __syncthreads();
        { int tmp = wo_c; wo_c = wo_n; wo_n = tmp; }

        // --- S step: prefetch V(tt); compute S; gather+mask ---
        load_tile(smc, wo_n, g_v + hoff, m0k, t, 0);
        gemm_tile(acc, qf, sbase + (uint32_t)wo_c, boff);

        const int ph = (tt & 1) << 6;   // ring phase offset
        #pragma unroll
        for (int f = 0; f < 8; f++) {
            int mi = 8 * f + 2 * tq;
            #pragma unroll
            for (int c = 0; c < 2; c++) {
                int cc = 63 - rt0 + mi + c;
                float rel = __half2float(pan[rt0 * PSTRIDE + ((cc + ph) & 127)]);
                float sv  = (acc[f][c] + rel) * SCL;
                acc[f][c] = (m0k + mi + c <= l0 + rt0) ? sv : -1e30f;
            }
            #pragma unroll
            for (int c = 0; c < 2; c++) {
                int cc = 63 - rt1 + mi + c;
                float rel = __half2float(pan[rt1 * PSTRIDE + ((cc + ph) & 127)]);
                float sv  = (acc[f][2 + c] + rel) * SCL;
                acc[f][2 + c] = (m0k + mi + c <= l0 + rt1) ? sv : -1e30f;
            }
        }

        // --- online softmax bookkeeping (log2 domain) ---
        float mx0 = -1e30f, mx1 = -1e30f;
        #pragma unroll
        for (int f = 0; f < 8; f++) {
            mx0 = fmaxf(mx0, fmaxf(acc[f][0], acc[f][1]));
            mx1 = fmaxf(mx1, fmaxf(acc[f][2], acc[f][3]));
        }
        mx0 = fmaxf(mx0, __shfl_xor_sync(0xffffffffu, mx0, 1));
        mx0 = fmaxf(mx0, __shfl_xor_sync(0xffffffffu, mx0, 2));
        mx1 = fmaxf(mx1, __shfl_xor_sync(0xffffffffu, mx1, 1));
        mx1 = fmaxf(mx1, __shfl_xor_sync(0xffffffffu, mx1, 2));
        float mn0 = fmaxf(rm0, mx0), mn1 = fmaxf(rm1, mx1);
        float cr0 = fex2(rm0 - mn0), cr1 = fex2(rm1 - mn1);
        rm0 = mn0; rm1 = mn1;
        // d = S - max (in place), rescale Oa
        #pragma unroll
        for (int f = 0; f < 8; f++) {
            acc[f][0] -= mn0; acc[f][1] -= mn0;
            acc[f][2] -= mn1; acc[f][3] -= mn1;
            Oa[f][0] *= cr0; Oa[f][1] *= cr0;
            Oa[f][2] *= cr1; Oa[f][3] *= cr1;
        }
        __syncthreads();   // V visible
        { int tmp = wo_c; wo_c = wo_n; wo_n = tmp; }

        // --- PV step: prefetch E for next tile; P = 2^d (f16x2);
        //     row sums via ones-MMA; O += P @ V ---
        if (tt + 1 < ntiles)
            load_tile(smc, wo_n, g_e, jb + 64 * (tt + 2), t, 1);

        float ls[4] = {0.f, 0.f, 0.f, 0.f};
        #pragma unroll
        for (int kc = 0; kc < 4; kc++) {
            uint32_t pha[4];
            pha[0] = h2ex2(pack2h(acc[2 * kc][0],     acc[2 * kc][1]));
            pha[1] = h2ex2(pack2h(acc[2 * kc][2],     acc[2 * kc][3]));
            pha[2] = h2ex2(pack2h(acc[2 * kc + 1][0], acc[2 * kc + 1][1]));
            pha[3] = h2ex2(pack2h(acc[2 * kc + 1][2], acc[2 * kc + 1][3]));
            mma_f16(ls, pha, ONESH2, ONESH2);   // fp32-exact row sums
            #pragma unroll
            for (int nb = 0; nb < 4; nb++) {
                uint32_t vh_[4];
                ldsm4t(vh_, sbase + (uint32_t)wo_c
                             + (uint32_t)(kc * 16 * TSTRIDE + nb * 32) + voff);
                mma_f16(Oa[2 * nb],     pha, vh_[0], vh_[1]);
                mma_f16(Oa[2 * nb + 1], pha, vh_[2], vh_[3]);
            }
        }
        rl0 = rl0 * cr0 + ls[0];
        rl1 = rl1 * cr1 + ls[2];
        __syncthreads();
        { int tmp = wo_c; wo_c = wo_n; wo_n = tmp; }
    }

    // epilogue: fp16 output (fc rounds to fp16 anyway)
    float inv0 = 1.0f / rl0, inv1 = 1.0f / rl1;
    __half* op = g_oh + hoff;
    #pragma unroll
    for (int f = 0; f < 8; f++) {
        int col = 8 * f + 2 * tq;
        *(uint32_t*)(op + (size_t)(l0 + rt0) * DH_ + col) =
            pack2h(Oa[f][0] * inv0, Oa[f][1] * inv0);
        *(uint32_t*)(op + (size_t)(l0 + rt1) * DH_ + col) =
            pack2h(Oa[f][2] * inv1, Oa[f][3] * inv1);
    }
}

// ---------------------------------------------------------------------------
extern "C" void kernel_launch(void* const* d_in, const int* in_sizes, int n_in,
                              void* d_out, int out_size)
{
    const float* Q  = (const float*)d_in[0];
    const float* K  = (const float*)d_in[1];
    const float* V  = (const float*)d_in[2];
    // d_in[3] = mask (causal, known analytically) - unused
    const float* Wq = (const float*)d_in[4];
    const float* bq = (const float*)d_in[5];
    const float* Wk = (const float*)d_in[6];
    const float* bk = (const float*)d_in[7];
    const float* Wv = (const float*)d_in[8];
    const float* bv = (const float*)d_in[9];
    const float* Wf = (const float*)d_in[10];
    const float* bf = (const float*)d_in[11];
    const float* E  = (const float*)d_in[12];
    // d_in[13] = H (known constant 8) - unused
    float* out = (float*)d_out;

    (void)in_sizes; (void)n_in; (void)out_size;

    eprep_kernel<<<(L_ * DH_ + 255) / 256, 256>>>(E);
    wprep_kernel<<<(D_ * D_ + 255) / 256, 256>>>(Wq, Wk, Wv, Wf);

    cudaFuncSetAttribute(proj_mma_kernel, cudaFuncAttributeMaxDynamicSharedMemorySize,
                         GEMM_SMEM);
    cudaFuncSetAttribute(fc_mma_kernel, cudaFuncAttributeMaxDynamicSharedMemorySize,
                         GEMM_SMEM);
    cudaFuncSetAttribute(attn_kernel, cudaFuncAttributeMaxDynamicSharedMemorySize,
                         ATTN_SMEM);

    dim3 gproj(NTOK / 128, D_ / 128, 3);
    proj_mma_kernel<<<gproj, 256, GEMM_SMEM>>>(Q, K, V, bq, bk, bv);

    dim3 gattn(L_ / 64, B_ * H_);
    attn_kernel<<<gattn, 128, ATTN_SMEM>>>();

    dim3 gfc(NTOK / 128, D_ / 128);
    fc_mma_kernel<<<gfc, 256, GEMM_SMEM>>>(bf, out);
}

// round 11
// speedup vs baseline: 1.2425x; 1.0427x over previous
#include <cuda_runtime.h>
#include <cuda_fp16.h>
#include <math.h>
#include <stdint.h>

#define B_  4
#define L_  2048
#define D_  512
#define H_  8
#define DH_ 64
#define NTOK (B_ * L_)   // 8192

// Scratch (allocation-free rule: __device__ globals).
__device__ __half g_q[(size_t)B_ * H_ * L_ * DH_];
__device__ __half g_k[(size_t)B_ * H_ * L_ * DH_];
__device__ __half g_v[(size_t)B_ * H_ * L_ * DH_];
__device__ __half g_e[(size_t)L_ * DH_];
__device__ __half g_oh[(size_t)B_ * H_ * L_ * DH_];
__device__ __half g_wq[(size_t)D_ * D_];
__device__ __half g_wk[(size_t)D_ * D_];
__device__ __half g_wv[(size_t)D_ * D_];
__device__ __half g_wf[(size_t)D_ * D_];

// ===========================================================================
// helpers
// ===========================================================================
__device__ __forceinline__ uint32_t smem_u32(const void* p) {
    uint32_t a;
    asm("{ .reg .u64 t; cvta.to.shared.u64 t, %1; cvt.u32.u64 %0, t; }"
        : "=r"(a) : "l"(p));
    return a;
}

__device__ __forceinline__ uint32_t pack2h(float x, float y) {
    __half2 h = __floats2half2_rn(x, y);
    return *reinterpret_cast<uint32_t*>(&h);
}

__device__ __forceinline__ float fex2(float x) {
    float r;
    asm("ex2.approx.f32 %0, %1;" : "=f"(r) : "f"(x));
    return r;
}

__device__ __forceinline__ uint32_t h2ex2(uint32_t x) {
    uint32_t r;
    asm("ex2.approx.f16x2 %0, %1;" : "=r"(r) : "r"(x));
    return r;
}

__device__ __forceinline__ void mma_f16(float c[4], const uint32_t a[4],
                                        uint32_t b0, uint32_t b1) {
    asm volatile(
        "mma.sync.aligned.m16n8k16.row.col.f32.f16.f16.f32 "
        "{%0,%1,%2,%3}, {%4,%5,%6,%7}, {%8,%9}, {%0,%1,%2,%3};"
        : "+f"(c[0]), "+f"(c[1]), "+f"(c[2]), "+f"(c[3])
        : "r"(a[0]), "r"(a[1]), "r"(a[2]), "r"(a[3]), "r"(b0), "r"(b1));
}

__device__ __forceinline__ void ldsm4(uint32_t r[4], uint32_t addr) {
    asm volatile("ldmatrix.sync.aligned.m8n8.x4.shared.b16 {%0,%1,%2,%3}, [%4];"
                 : "=r"(r[0]), "=r"(r[1]), "=r"(r[2]), "=r"(r[3]) : "r"(addr));
}
__device__ __forceinline__ void ldsm4t(uint32_t r[4], uint32_t addr) {
    asm volatile("ldmatrix.sync.aligned.m8n8.x4.trans.shared.b16 {%0,%1,%2,%3}, [%4];"
                 : "=r"(r[0]), "=r"(r[1]), "=r"(r[2]), "=r"(r[3]) : "r"(addr));
}

// cp.async (sm_80 baseline feature — legal on compute_103)
__device__ __forceinline__ void cpa16(uint32_t s, const void* g) {
    asm volatile("cp.async.ca.shared.global [%0], [%1], 16;" :: "r"(s), "l"(g));
}
__device__ __forceinline__ void cpa8(uint32_t s, const void* g) {
    asm volatile("cp.async.ca.shared.global [%0], [%1], 8;" :: "r"(s), "l"(g));
}
__device__ __forceinline__ void cpa_wait() {
    asm volatile("cp.async.commit_group;" ::: "memory");
    asm volatile("cp.async.wait_group 0;" ::: "memory");
}

// ---------------------------------------------------------------------------
// prep kernels: E -> fp16, weights -> fp16
// ---------------------------------------------------------------------------
__global__ void eprep_kernel(const float* __restrict__ E) {
    int i = blockIdx.x * 256 + threadIdx.x;
    if (i < L_ * DH_) g_e[i] = __float2half_rn(E[i]);
}

__global__ void wprep_kernel(const float* __restrict__ Wq, const float* __restrict__ Wk,
                             const float* __restrict__ Wv, const float* __restrict__ Wf) {
    int i = blockIdx.x * 256 + threadIdx.x;
    if (i < D_ * D_) {
        g_wq[i] = __float2half_rn(Wq[i]);
        g_wk[i] = __float2half_rn(Wk[i]);
        g_wv[i] = __float2half_rn(Wv[i]);
        g_wf[i] = __float2half_rn(Wf[i]);
    }
}

// ===========================================================================
// MMA GEMM machinery (128x128 CTA tile, 256 threads, 8 warps 4x2,
// warp tile 32x64, K chunk 64, 2-stage smem double buffer, plain fp16,
// fp16 weights in gmem, cp.async for fp16 panels).
// ===========================================================================
#define GSTRIDE 144
#define PANEL   18432
#define STAGE   36864
#define GEMM_SMEM (2 * STAGE)
#define KCH 8

__device__ __forceinline__ void cvt_sts(char* smc, uint32_t off, float4 v) {
    *(uint2*)(smc + off) = make_uint2(pack2h(v.x, v.y), pack2h(v.z, v.w));
}

__device__ __forceinline__ void gemm_chunk(uint32_t stg, int warp_m, int warp_n,
                                           int ln, float acc[2][8][4])
{
    const uint32_t aoff = (uint32_t)((ln & 15) * GSTRIDE + (ln >> 4) * 16);
    const uint32_t boff = (uint32_t)(((ln & 7) + ((ln >> 4) << 3)) * GSTRIDE
                                     + (((ln >> 3) & 1) << 4));
    #pragma unroll
    for (int ks = 0; ks < 4; ks++) {
        uint32_t ah[2][4];
        #pragma unroll
        for (int mb = 0; mb < 2; mb++)
            ldsm4(ah[mb], stg + (uint32_t)((warp_m * 32 + mb * 16) * GSTRIDE + ks * 32) + aoff);
        #pragma unroll
        for (int nb = 0; nb < 4; nb++) {
            uint32_t bh_[4];
            ldsm4(bh_, stg + PANEL
                       + (uint32_t)((warp_n * 64 + nb * 16) * GSTRIDE + ks * 32) + boff);
            #pragma unroll
            for (int mb = 0; mb < 2; mb++) {
                mma_f16(acc[mb][2 * nb],     ah[mb], bh_[0], bh_[1]);
                mma_f16(acc[mb][2 * nb + 1], ah[mb], bh_[2], bh_[3]);
            }
        }
    }
}

// ---------------------------------------------------------------------------
// QKV projection on tensor cores -> fp16 head layout.
// ---------------------------------------------------------------------------
__global__ __launch_bounds__(256, 2) void proj_mma_kernel(
    const float* __restrict__ Xq, const float* __restrict__ Xk, const float* __restrict__ Xv,
    const float* __restrict__ bq, const float* __restrict__ bk, const float* __restrict__ bv)
{
    extern __shared__ char smc[];
    const uint32_t sbase = smem_u32(smc);

    const float *X, *bias;
    const __half* Wh;
    __half* Y;
    if (blockIdx.z == 0)      { X = Xq; Wh = g_wq; bias = bq; Y = g_q; }
    else if (blockIdx.z == 1) { X = Xk; Wh = g_wk; bias = bk; Y = g_k; }
    else                      { X = Xv; Wh = g_wv; bias = bv; Y = g_v; }

    const int t   = threadIdx.x;
    const int wid = t >> 5;
    const int ln  = t & 31;
    const int warp_m = wid >> 1;
    const int warp_n = wid & 1;
    const int m0 = blockIdx.x * 128;
    const int n0 = blockIdx.y * 128;

    auto loadsts = [&](int k0, uint32_t so) {
        #pragma unroll
        for (int r = 0; r < 8; r++) {
            int idx = t + r * 256;
            int row = idx >> 4;
            int cg  = idx & 15;
            uint32_t o = so + (uint32_t)(row * GSTRIDE + cg * 8);
            cvt_sts(smc, o, *(const float4*)(X + (size_t)(m0 + row) * D_ + k0 + cg * 4));
            cpa8(sbase + o + PANEL, Wh + (size_t)(n0 + row) * D_ + k0 + cg * 4);
        }
    };

    float acc[2][8][4] = {};

    loadsts(0, 0);
    cpa_wait();
    __syncthreads();

    for (int p = 0; p < KCH; p++) {
        const int s = p & 1;
        gemm_chunk(sbase + (uint32_t)s * STAGE, warp_m, warp_n, ln, acc);
        if (p < KCH - 1) loadsts((p + 1) * 64, (uint32_t)(s ^ 1) * STAGE);
        cpa_wait();
        __syncthreads();
    }

    const int g  = ln >> 2;
    const int tq = ln & 3;
    #pragma unroll
    for (int mb = 0; mb < 2; mb++) {
        int r0 = m0 + warp_m * 32 + mb * 16 + g;
        int r1 = r0 + 8;
        int bb0 = r0 >> 11, ll0 = r0 & (L_ - 1);
        int bb1 = r1 >> 11, ll1 = r1 & (L_ - 1);
        #pragma unroll
        for (int f = 0; f < 8; f++) {
            int col = n0 + warp_n * 64 + f * 8 + 2 * tq;
            int hh = col >> 6, dh = col & 63;
            float b0 = bias[col], b1 = bias[col + 1];
            size_t o0 = (((size_t)bb0 * H_ + hh) * L_ + ll0) * DH_ + dh;
            *(uint32_t*)(Y + o0) = pack2h(acc[mb][f][0] + b0, acc[mb][f][1] + b1);
            size_t o1 = (((size_t)bb1 * H_ + hh) * L_ + ll1) * DH_ + dh;
            *(uint32_t*)(Y + o1) = pack2h(acc[mb][f][2] + b0, acc[mb][f][3] + b1);
        }
    }
}

// ---------------------------------------------------------------------------
// Output projection: gathers fp16 (B,H,L,DH) rows from g_oh -> fp32 out.
// ---------------------------------------------------------------------------
__global__ __launch_bounds__(256, 2) void fc_mma_kernel(
    const float* __restrict__ bf, float* __restrict__ out)
{
    extern __shared__ char smc[];
    const uint32_t sbase = smem_u32(smc);

    const int t   = threadIdx.x;
    const int wid = t >> 5;
    const int ln  = t & 31;
    const int warp_m = wid >> 1;
    const int warp_n = wid & 1;
    const int m0 = blockIdx.x * 128;
    const int n0 = blockIdx.y * 128;

    auto loadsts = [&](int k0, uint32_t so) {
        #pragma unroll
        for (int r = 0; r < 8; r++) {
            int idx = t + r * 256;
            int row = idx >> 4;
            int cg  = idx & 15;
            int n   = m0 + row;
            int bb  = n >> 11, ll = n & (L_ - 1);
            int d   = k0 + cg * 4;
            int hh  = d >> 6, dh = d & 63;
            uint32_t o = so + (uint32_t)(row * GSTRIDE + cg * 8);
            cpa8(sbase + o,
                 g_oh + (((size_t)bb * H_ + hh) * L_ + ll) * DH_ + dh);
            cpa8(sbase + o + PANEL,
                 g_wf + (size_t)(n0 + row) * D_ + k0 + cg * 4);
        }
    };

    float acc[2][8][4] = {};

    loadsts(0, 0);
    cpa_wait();
    __syncthreads();

    for (int p = 0; p < KCH; p++) {
        const int s = p & 1;
        gemm_chunk(sbase + (uint32_t)s * STAGE, warp_m, warp_n, ln, acc);
        if (p < KCH - 1) loadsts((p + 1) * 64, (uint32_t)(s ^ 1) * STAGE);
        cpa_wait();
        __syncthreads();
    }

    const int g  = ln >> 2;
    const int tq = ln & 3;
    #pragma unroll
    for (int mb = 0; mb < 2; mb++) {
        int r0 = m0 + warp_m * 32 + mb * 16 + g;
        int r1 = r0 + 8;
        #pragma unroll
        for (int f = 0; f < 8; f++) {
            int col = n0 + warp_n * 64 + f * 8 + 2 * tq;
            float b0 = bf[col], b1 = bf[col + 1];
            *(float2*)(out + (size_t)r0 * D_ + col) =
                make_float2(acc[mb][f][0] + b0, acc[mb][f][1] + b1);
            *(float2*)(out + (size_t)r1 * D_ + col) =
                make_float2(acc[mb][f][2] + b0, acc[mb][f][3] + b1);
        }
    }
}

// ===========================================================================
// Attention: flash-style causal + rel-pos, plain fp16 mma.sync.
// Tq=128, 256 threads (8 warps, each owns 16 q rows). Key tiles of 64.
// 4-slot fp16 QE panel ring (256 cols, power-of-2 wrap), cp.async tile loads,
// f16x2 exp softmax, MMA row sums.
// smem: Pan fp16 128x264 @0 (67584 B; Q tile 128x144 aliases in prologue) |
//       WKA @67584 (9216) | WKB @76800 (9216).  Total 86016 B.
// ===========================================================================
#define PAN     0
#define QH_OFF  0
#define WKA     67584
#define WKB     76800
#define ATTN_SMEM 86016
#define TSTRIDE 144   // bytes per smem tile row (72 fp16)
#define PSTRIDE 264   // halves per panel row (256 ring + 8 pad)
#define SCL 0.18033688011112042f   // 0.125 * log2(e)
#define ONESH2 0x3C003C00u         // half2 (1.0, 1.0)

__device__ __forceinline__ void load_tile64(uint32_t sbase, uint32_t woff,
    const __half* __restrict__ src, int rowbase, int t, int clampE)
{
    #pragma unroll
    for (int r = 0; r < 2; r++) {
        int idx = t + r * 256;
        int row = idx >> 3, c8 = idx & 7;
        int gr = rowbase + row;
        if (clampE) gr = (gr < L_) ? gr : (L_ - 1);
        cpa16(sbase + woff + (uint32_t)(row * TSTRIDE + c8 * 16),
              src + (size_t)gr * DH_ + c8 * 8);
    }
}

// acc[8][4] = Qwarp(16 x 64) * tile(64 x 64)^T, plain fp16
__device__ __forceinline__ void gemm_tile(float acc[8][4],
    const uint32_t qf[4][4], uint32_t th, uint32_t boff)
{
    #pragma unroll
    for (int f = 0; f < 8; f++)
        #pragma unroll
        for (int c = 0; c < 4; c++) acc[f][c] = 0.f;
    #pragma unroll
    for (int kc = 0; kc < 4; kc++) {
        #pragma unroll
        for (int nbp = 0; nbp < 4; nbp++) {
            uint32_t bh_[4];
            ldsm4(bh_, th + (uint32_t)(nbp * 16 * TSTRIDE + kc * 32) + boff);
            mma_f16(acc[2 * nbp],     qf[kc], bh_[0], bh_[1]);
            mma_f16(acc[2 * nbp + 1], qf[kc], bh_[2], bh_[3]);
        }
    }
}

// store one QE panel into ring slot (physical columns [slot*64, slot*64+64))
__device__ __forceinline__ void store_panel(__half* pan, const float acc[8][4],
                                            int prow, int tq, int slot)
{
    #pragma unroll
    for (int f = 0; f < 8; f++) {
        *(uint32_t*)&pan[prow * PSTRIDE + slot * 64 + 8 * f + 2 * tq] =
            pack2h(acc[f][0], acc[f][1]);
        *(uint32_t*)&pan[(prow + 8) * PSTRIDE + slot * 64 + 8 * f + 2 * tq] =
            pack2h(acc[f][2], acc[f][3]);
    }
}

__global__ __launch_bounds__(256, 2) void attn_kernel()
{
    extern __shared__ char smc[];
    const uint32_t sbase = smem_u32(smc);
    __half* pan = (__half*)smc;

    const int t  = threadIdx.x;
    const int w  = t >> 5;            // 0..7, warp owns q rows [w*16, w*16+16)
    const int ln = t & 31;
    const int g  = ln >> 2;
    const int tq = ln & 3;
    const int qt = (int)(gridDim.x - 1) - (int)blockIdx.x;  // heavy first
    const int l0 = qt * 128;
    const int bh = blockIdx.y;

    const size_t hoff = (size_t)bh * L_ * DH_;

    const uint32_t aoff = (uint32_t)((w * 16 + (ln & 15)) * TSTRIDE + (ln >> 4) * 16);
    const uint32_t boff = (uint32_t)(((ln & 7) + ((ln >> 4) << 3)) * TSTRIDE + (((ln >> 3) & 1) << 4));
    const uint32_t voff = (uint32_t)(((ln & 7) + (((ln >> 3) & 1) << 3)) * TSTRIDE + ((ln >> 4) << 4));

    // prologue: Q tile (128 rows, aliases panel), E slot-0 tile -> WKA
    #pragma unroll
    for (int r = 0; r < 4; r++) {
        int idx = t + r * 256;
        int row = idx >> 3, c8 = idx & 7;
        cpa16(sbase + QH_OFF + (uint32_t)(row * TSTRIDE + c8 * 16),
              g_q + hoff + (size_t)(l0 + row) * DH_ + c8 * 8);
    }
    const int eb = L_ - 128 - l0;
    load_tile64(sbase, WKA, g_e, eb, t, 1);
    cpa_wait();
    __syncthreads();

    uint32_t qf[4][4];
    #pragma unroll
    for (int kc = 0; kc < 4; kc++)
        ldsm4(qf[kc], sbase + QH_OFF + kc * 32 + aoff);
    __syncthreads();   // Q smem dead; panel ring writable

    const int rt0 = w * 16 + g;
    const int rt1 = rt0 + 8;
    float acc[8][4];

    // prologue panel 0 (from WKA); prefetch E slot 1 -> WKB
    load_tile64(sbase, WKB, g_e, eb + 64, t, 1);
    gemm_tile(acc, qf, sbase + WKA, boff);
    store_panel(pan, acc, rt0, tq, 0);
    cpa_wait();
    __syncthreads();

    // prologue panel 1 (from WKB); prefetch E slot 2 -> WKA
    load_tile64(sbase, WKA, g_e, eb + 128, t, 1);
    gemm_tile(acc, qf, sbase + WKB, boff);
    store_panel(pan, acc, rt0, tq, 1);
    cpa_wait();
    __syncthreads();

    uint32_t wo_c = WKA, wo_n = WKB;   // WKA holds E slot-2 tile

    float Oa[8][4] = {};
    float rm0 = -1e30f, rm1 = -1e30f, rl0 = 0.f, rl1 = 0.f;

    const int ntiles = 2 * qt + 2;

    for (int tt = 0; tt < ntiles; tt++) {
        const int m0k = tt * 64;

        // --- QE step: prefetch K(tt); compute QE panel -> slot (tt+2)&3 ---
        load_tile64(sbase, wo_n, g_k + hoff, m0k, t, 0);
        gemm_tile(acc, qf, sbase + wo_c, boff);
        store_panel(pan, acc, rt0, tq, (tt + 2) & 3);
        cpa_wait();
        __syncthreads();
        { uint32_t tmp = wo_c; wo_c = wo_n; wo_n = tmp; }

        // --- S step: prefetch V(tt); compute S; gather+mask ---
        load_tile64(sbase, wo_n, g_v + hoff, m0k, t, 0);
        gemm_tile(acc, qf, sbase + wo_c, boff);

        // ring position: p = 64*tt + 127 - li + mi + c  (mod 256), mi = 8f+2tq
        const int ofs0 = 64 * tt + 127 - rt0 + 2 * tq;
        const int ofs1 = ofs0 - 8;
        const int lim0 = l0 + rt0 - m0k - 2 * tq;   // unmasked iff 8f + c <= lim0
        const int lim1 = lim0 + 8;
        #pragma unroll
        for (int f = 0; f < 8; f++) {
            #pragma unroll
            for (int c = 0; c < 2; c++) {
                int p0 = (ofs0 + 8 * f + c) & 255;
                float rel0 = __half2float(pan[rt0 * PSTRIDE + p0]);
                float sv0  = (acc[f][c] + rel0) * SCL;
                acc[f][c]  = (8 * f + c <= lim0) ? sv0 : -1e30f;
                int p1 = (ofs1 + 8 * f + c) & 255;
                float rel1 = __half2float(pan[rt1 * PSTRIDE + p1]);
                float sv1  = (acc[f][2 + c] + rel1) * SCL;
                acc[f][2 + c] = (8 * f + c <= lim1) ? sv1 : -1e30f;
            }
        }

        // --- online softmax bookkeeping (log2 domain) ---
        float mx0 = -1e30f, mx1 = -1e30f;
        #pragma unroll
        for (int f = 0; f < 8; f++) {
            mx0 = fmaxf(mx0, fmaxf(acc[f][0], acc[f][1]));
            mx1 = fmaxf(mx1, fmaxf(acc[f][2], acc[f][3]));
        }
        mx0 = fmaxf(mx0, __shfl_xor_sync(0xffffffffu, mx0, 1));
        mx0 = fmaxf(mx0, __shfl_xor_sync(0xffffffffu, mx0, 2));
        mx1 = fmaxf(mx1, __shfl_xor_sync(0xffffffffu, mx1, 1));
        mx1 = fmaxf(mx1, __shfl_xor_sync(0xffffffffu, mx1, 2));
        float mn0 = fmaxf(rm0, mx0), mn1 = fmaxf(rm1, mx1);
        float cr0 = fex2(rm0 - mn0), cr1 = fex2(rm1 - mn1);
        rm0 = mn0; rm1 = mn1;
        #pragma unroll
        for (int f = 0; f < 8; f++) {
            acc[f][0] -= mn0; acc[f][1] -= mn0;
            acc[f][2] -= mn1; acc[f][3] -= mn1;
            Oa[f][0] *= cr0; Oa[f][1] *= cr0;
            Oa[f][2] *= cr1; Oa[f][3] *= cr1;
        }
        cpa_wait();
        __syncthreads();   // V visible
        { uint32_t tmp = wo_c; wo_c = wo_n; wo_n = tmp; }

        // --- PV step: prefetch E slot (tt+3); P = 2^d; sums via MMA; PV ---
        if (tt + 1 < ntiles)
            load_tile64(sbase, wo_n, g_e, eb + 64 * (tt + 3), t, 1);

        float ls[4] = {0.f, 0.f, 0.f, 0.f};
        #pragma unroll
        for (int kc = 0; kc < 4; kc++) {
            uint32_t pha[4];
            pha[0] = h2ex2(pack2h(acc[2 * kc][0],     acc[2 * kc][1]));
            pha[1] = h2ex2(pack2h(acc[2 * kc][2],     acc[2 * kc][3]));
            pha[2] = h2ex2(pack2h(acc[2 * kc + 1][0], acc[2 * kc + 1][1]));
            pha[3] = h2ex2(pack2h(acc[2 * kc + 1][2], acc[2 * kc + 1][3]));
            mma_f16(ls, pha, ONESH2, ONESH2);   // fp32-exact row sums
            #pragma unroll
            for (int nb = 0; nb < 4; nb++) {
                uint32_t vh_[4];
                ldsm4t(vh_, sbase + wo_c
                             + (uint32_t)(kc * 16 * TSTRIDE + nb * 32) + voff);
                mma_f16(Oa[2 * nb],     pha, vh_[0], vh_[1]);
                mma_f16(Oa[2 * nb + 1], pha, vh_[2], vh_[3]);
            }
        }
        rl0 = rl0 * cr0 + ls[0];
        rl1 = rl1 * cr1 + ls[2];
        cpa_wait();
        __syncthreads();
        { uint32_t tmp = wo_c; wo_c = wo_n; wo_n = tmp; }
    }

    // epilogue: fp16 output (fc rounds to fp16 anyway)
    float inv0 = 1.0f / rl0, inv1 = 1.0f / rl1;
    __half* op = g_oh + hoff;
    #pragma unroll
    for (int f = 0; f < 8; f++) {
        int col = 8 * f + 2 * tq;
        *(uint32_t*)(op + (size_t)(l0 + rt0) * DH_ + col) =
            pack2h(Oa[f][0] * inv0, Oa[f][1] * inv0);
        *(uint32_t*)(op + (size_t)(l0 + rt1) * DH_ + col) =
            pack2h(Oa[f][2] * inv1, Oa[f][3] * inv1);
    }
}

// ---------------------------------------------------------------------------
extern "C" void kernel_launch(void* const* d_in, const int* in_sizes, int n_in,
                              void* d_out, int out_size)
{
    const float* Q  = (const float*)d_in[0];
    const float* K  = (const float*)d_in[1];
    const float* V  = (const float*)d_in[2];
    // d_in[3] = mask (causal, known analytically) - unused
    const float* Wq = (const float*)d_in[4];
    const float* bq = (const float*)d_in[5];
    const float* Wk = (const float*)d_in[6];
    const float* bk = (const float*)d_in[7];
    const float* Wv = (const float*)d_in[8];
    const float* bv = (const float*)d_in[9];
    const float* Wf = (const float*)d_in[10];
    const float* bf = (const float*)d_in[11];
    const float* E  = (const float*)d_in[12];
    // d_in[13] = H (known constant 8) - unused
    float* out = (float*)d_out;

    (void)in_sizes; (void)n_in; (void)out_size;

    eprep_kernel<<<(L_ * DH_ + 255) / 256, 256>>>(E);
    wprep_kernel<<<(D_ * D_ + 255) / 256, 256>>>(Wq, Wk, Wv, Wf);

    cudaFuncSetAttribute(proj_mma_kernel, cudaFuncAttributeMaxDynamicSharedMemorySize,
                         GEMM_SMEM);
    cudaFuncSetAttribute(fc_mma_kernel, cudaFuncAttributeMaxDynamicSharedMemorySize,
                         GEMM_SMEM);
    cudaFuncSetAttribute(attn_kernel, cudaFuncAttributeMaxDynamicSharedMemorySize,
                         ATTN_SMEM);

    dim3 gproj(NTOK / 128, D_ / 128, 3);
    proj_mma_kernel<<<gproj, 256, GEMM_SMEM>>>(Q, K, V, bq, bk, bv);

    dim3 gattn(L_ / 128, B_ * H_);
    attn_kernel<<<gattn, 256, ATTN_SMEM>>>();

    dim3 gfc(NTOK / 128, D_ / 128);
    fc_mma_kernel<<<gfc, 256, GEMM_SMEM>>>(bf, out);
}

// round 12
// speedup vs baseline: 1.2577x; 1.0123x over previous
#include <cuda_runtime.h>
#include <cuda_fp16.h>
#include <math.h>
#include <stdint.h>

#define B_  4
#define L_  2048
#define D_  512
#define H_  8
#define DH_ 64
#define NTOK (B_ * L_)   // 8192

// Scratch (allocation-free rule: __device__ globals).
__device__ __half g_q[(size_t)B_ * H_ * L_ * DH_];
__device__ __half g_k[(size_t)B_ * H_ * L_ * DH_];
__device__ __half g_v[(size_t)B_ * H_ * L_ * DH_];
__device__ __half g_e[(size_t)L_ * DH_];
__device__ __half g_oh[(size_t)B_ * H_ * L_ * DH_];
__device__ __half g_wq[(size_t)D_ * D_];
__device__ __half g_wk[(size_t)D_ * D_];
__device__ __half g_wv[(size_t)D_ * D_];
__device__ __half g_wf[(size_t)D_ * D_];

// ===========================================================================
// helpers
// ===========================================================================
__device__ __forceinline__ uint32_t smem_u32(const void* p) {
    uint32_t a;
    asm("{ .reg .u64 t; cvta.to.shared.u64 t, %1; cvt.u32.u64 %0, t; }"
        : "=r"(a) : "l"(p));
    return a;
}

__device__ __forceinline__ uint32_t pack2h(float x, float y) {
    __half2 h = __floats2half2_rn(x, y);
    return *reinterpret_cast<uint32_t*>(&h);
}

__device__ __forceinline__ float fex2(float x) {
    float r;
    asm("ex2.approx.f32 %0, %1;" : "=f"(r) : "f"(x));
    return r;
}

__device__ __forceinline__ uint32_t h2ex2(uint32_t x) {
    uint32_t r;
    asm("ex2.approx.f16x2 %0, %1;" : "=r"(r) : "r"(x));
    return r;
}

__device__ __forceinline__ void mma_f16(float c[4], const uint32_t a[4],
                                        uint32_t b0, uint32_t b1) {
    asm volatile(
        "mma.sync.aligned.m16n8k16.row.col.f32.f16.f16.f32 "
        "{%0,%1,%2,%3}, {%4,%5,%6,%7}, {%8,%9}, {%0,%1,%2,%3};"
        : "+f"(c[0]), "+f"(c[1]), "+f"(c[2]), "+f"(c[3])
        : "r"(a[0]), "r"(a[1]), "r"(a[2]), "r"(a[3]), "r"(b0), "r"(b1));
}

__device__ __forceinline__ void ldsm4(uint32_t r[4], uint32_t addr) {
    asm volatile("ldmatrix.sync.aligned.m8n8.x4.shared.b16 {%0,%1,%2,%3}, [%4];"
                 : "=r"(r[0]), "=r"(r[1]), "=r"(r[2]), "=r"(r[3]) : "r"(addr));
}
__device__ __forceinline__ void ldsm4t(uint32_t r[4], uint32_t addr) {
    asm volatile("ldmatrix.sync.aligned.m8n8.x4.trans.shared.b16 {%0,%1,%2,%3}, [%4];"
                 : "=r"(r[0]), "=r"(r[1]), "=r"(r[2]), "=r"(r[3]) : "r"(addr));
}

// cp.async (sm_80 baseline feature — legal on compute_103)
__device__ __forceinline__ void cpa16(uint32_t s, const void* g) {
    asm volatile("cp.async.ca.shared.global [%0], [%1], 16;" :: "r"(s), "l"(g));
}
__device__ __forceinline__ void cpa8(uint32_t s, const void* g) {
    asm volatile("cp.async.ca.shared.global [%0], [%1], 8;" :: "r"(s), "l"(g));
}
__device__ __forceinline__ void cpa_wait() {
    asm volatile("cp.async.commit_group;" ::: "memory");
    asm volatile("cp.async.wait_group 0;" ::: "memory");
}

// ---------------------------------------------------------------------------
// prep kernels: E -> fp16, weights -> fp16
// ---------------------------------------------------------------------------
__global__ void eprep_kernel(const float* __restrict__ E) {
    int i = blockIdx.x * 256 + threadIdx.x;
    if (i < L_ * DH_) g_e[i] = __float2half_rn(E[i]);
}

__global__ void wprep_kernel(const float* __restrict__ Wq, const float* __restrict__ Wk,
                             const float* __restrict__ Wv, const float* __restrict__ Wf) {
    int i = blockIdx.x * 256 + threadIdx.x;
    if (i < D_ * D_) {
        g_wq[i] = __float2half_rn(Wq[i]);
        g_wk[i] = __float2half_rn(Wk[i]);
        g_wv[i] = __float2half_rn(Wv[i]);
        g_wf[i] = __float2half_rn(Wf[i]);
    }
}

// ===========================================================================
// MMA GEMM machinery (identical to R11 — known-good).
// ===========================================================================
#define GSTRIDE 144
#define PANEL   18432
#define STAGE   36864
#define GEMM_SMEM (2 * STAGE)
#define KCH 8

__device__ __forceinline__ void cvt_sts(char* smc, uint32_t off, float4 v) {
    *(uint2*)(smc + off) = make_uint2(pack2h(v.x, v.y), pack2h(v.z, v.w));
}

__device__ __forceinline__ void gemm_chunk(uint32_t stg, int warp_m, int warp_n,
                                           int ln, float acc[2][8][4])
{
    const uint32_t aoff = (uint32_t)((ln & 15) * GSTRIDE + (ln >> 4) * 16);
    const uint32_t boff = (uint32_t)(((ln & 7) + ((ln >> 4) << 3)) * GSTRIDE
                                     + (((ln >> 3) & 1) << 4));
    #pragma unroll
    for (int ks = 0; ks < 4; ks++) {
        uint32_t ah[2][4];
        #pragma unroll
        for (int mb = 0; mb < 2; mb++)
            ldsm4(ah[mb], stg + (uint32_t)((warp_m * 32 + mb * 16) * GSTRIDE + ks * 32) + aoff);
        #pragma unroll
        for (int nb = 0; nb < 4; nb++) {
            uint32_t bh_[4];
            ldsm4(bh_, stg + PANEL
                       + (uint32_t)((warp_n * 64 + nb * 16) * GSTRIDE + ks * 32) + boff);
            #pragma unroll
            for (int mb = 0; mb < 2; mb++) {
                mma_f16(acc[mb][2 * nb],     ah[mb], bh_[0], bh_[1]);
                mma_f16(acc[mb][2 * nb + 1], ah[mb], bh_[2], bh_[3]);
            }
        }
    }
}

__global__ __launch_bounds__(256, 2) void proj_mma_kernel(
    const float* __restrict__ Xq, const float* __restrict__ Xk, const float* __restrict__ Xv,
    const float* __restrict__ bq, const float* __restrict__ bk, const float* __restrict__ bv)
{
    extern __shared__ char smc[];
    const uint32_t sbase = smem_u32(smc);

    const float *X, *bias;
    const __half* Wh;
    __half* Y;
    if (blockIdx.z == 0)      { X = Xq; Wh = g_wq; bias = bq; Y = g_q; }
    else if (blockIdx.z == 1) { X = Xk; Wh = g_wk; bias = bk; Y = g_k; }
    else                      { X = Xv; Wh = g_wv; bias = bv; Y = g_v; }

    const int t   = threadIdx.x;
    const int wid = t >> 5;
    const int ln  = t & 31;
    const int warp_m = wid >> 1;
    const int warp_n = wid & 1;
    const int m0 = blockIdx.x * 128;
    const int n0 = blockIdx.y * 128;

    auto loadsts = [&](int k0, uint32_t so) {
        #pragma unroll
        for (int r = 0; r < 8; r++) {
            int idx = t + r * 256;
            int row = idx >> 4;
            int cg  = idx & 15;
            uint32_t o = so + (uint32_t)(row * GSTRIDE + cg * 8);
            cvt_sts(smc, o, *(const float4*)(X + (size_t)(m0 + row) * D_ + k0 + cg * 4));
            cpa8(sbase + o + PANEL, Wh + (size_t)(n0 + row) * D_ + k0 + cg * 4);
        }
    };

    float acc[2][8][4] = {};

    loadsts(0, 0);
    cpa_wait();
    __syncthreads();

    for (int p = 0; p < KCH; p++) {
        const int s = p & 1;
        gemm_chunk(sbase + (uint32_t)s * STAGE, warp_m, warp_n, ln, acc);
        if (p < KCH - 1) loadsts((p + 1) * 64, (uint32_t)(s ^ 1) * STAGE);
        cpa_wait();
        __syncthreads();
    }

    const int g  = ln >> 2;
    const int tq = ln & 3;
    #pragma unroll
    for (int mb = 0; mb < 2; mb++) {
        int r0 = m0 + warp_m * 32 + mb * 16 + g;
        int r1 = r0 + 8;
        int bb0 = r0 >> 11, ll0 = r0 & (L_ - 1);
        int bb1 = r1 >> 11, ll1 = r1 & (L_ - 1);
        #pragma unroll
        for (int f = 0; f < 8; f++) {
            int col = n0 + warp_n * 64 + f * 8 + 2 * tq;
            int hh = col >> 6, dh = col & 63;
            float b0 = bias[col], b1 = bias[col + 1];
            size_t o0 = (((size_t)bb0 * H_ + hh) * L_ + ll0) * DH_ + dh;
            *(uint32_t*)(Y + o0) = pack2h(acc[mb][f][0] + b0, acc[mb][f][1] + b1);
            size_t o1 = (((size_t)bb1 * H_ + hh) * L_ + ll1) * DH_ + dh;
            *(uint32_t*)(Y + o1) = pack2h(acc[mb][f][2] + b0, acc[mb][f][3] + b1);
        }
    }
}

__global__ __launch_bounds__(256, 2) void fc_mma_kernel(
    const float* __restrict__ bf, float* __restrict__ out)
{
    extern __shared__ char smc[];
    const uint32_t sbase = smem_u32(smc);

    const int t   = threadIdx.x;
    const int wid = t >> 5;
    const int ln  = t & 31;
    const int warp_m = wid >> 1;
    const int warp_n = wid & 1;
    const int m0 = blockIdx.x * 128;
    const int n0 = blockIdx.y * 128;

    auto loadsts = [&](int k0, uint32_t so) {
        #pragma unroll
        for (int r = 0; r < 8; r++) {
            int idx = t + r * 256;
            int row = idx >> 4;
            int cg  = idx & 15;
            int n   = m0 + row;
            int bb  = n >> 11, ll = n & (L_ - 1);
            int d   = k0 + cg * 4;
            int hh  = d >> 6, dh = d & 63;
            uint32_t o = so + (uint32_t)(row * GSTRIDE + cg * 8);
            cpa8(sbase + o,
                 g_oh + (((size_t)bb * H_ + hh) * L_ + ll) * DH_ + dh);
            cpa8(sbase + o + PANEL,
                 g_wf + (size_t)(n0 + row) * D_ + k0 + cg * 4);
        }
    };

    float acc[2][8][4] = {};

    loadsts(0, 0);
    cpa_wait();
    __syncthreads();

    for (int p = 0; p < KCH; p++) {
        const int s = p & 1;
        gemm_chunk(sbase + (uint32_t)s * STAGE, warp_m, warp_n, ln, acc);
        if (p < KCH - 1) loadsts((p + 1) * 64, (uint32_t)(s ^ 1) * STAGE);
        cpa_wait();
        __syncthreads();
    }

    const int g  = ln >> 2;
    const int tq = ln & 3;
    #pragma unroll
    for (int mb = 0; mb < 2; mb++) {
        int r0 = m0 + warp_m * 32 + mb * 16 + g;
        int r1 = r0 + 8;
        #pragma unroll
        for (int f = 0; f < 8; f++) {
            int col = n0 + warp_n * 64 + f * 8 + 2 * tq;
            float b0 = bf[col], b1 = bf[col + 1];
            *(float2*)(out + (size_t)r0 * D_ + col) =
                make_float2(acc[mb][f][0] + b0, acc[mb][f][1] + b1);
            *(float2*)(out + (size_t)r1 * D_ + col) =
                make_float2(acc[mb][f][2] + b0, acc[mb][f][3] + b1);
        }
    }
}

// ===========================================================================
// Attention: flash-style causal + rel-pos, plain fp16 mma.sync.
// Tq=128, 256 threads (8 warps). 64-wide key tiles.
// NEW: fixed-role buffers (EK 128 rows, V 64 rows), 2 barriers/iteration,
// warp-private panel (syncwarp only), causal-masked warp skip, conditional
// Oa rescale.
// smem: Pan fp16 128x264 @0 (67584; Q aliases in prologue) |
//       BUF_EK @67584 (18432: E rows 0-63, K rows 64-127) |
//       BUF_V  @86016 (9216).  Total 95232 B.
// ===========================================================================
#define PAN     0
#define QH_OFF  0
#define BUF_EK  67584
#define BUF_K   (BUF_EK + 64 * TSTRIDE)
#define BUF_V   86016
#define ATTN_SMEM 95232
#define TSTRIDE 144   // bytes per smem tile row (72 fp16)
#define PSTRIDE 264   // halves per panel row (256 ring + 8 pad)
#define SCL 0.18033688011112042f   // 0.125 * log2(e)
#define ONESH2 0x3C003C00u         // half2 (1.0, 1.0)

__device__ __forceinline__ void load_tile64(uint32_t sbase, uint32_t woff,
    const __half* __restrict__ src, int rowbase, int t, int clampE)
{
    #pragma unroll
    for (int r = 0; r < 2; r++) {
        int idx = t + r * 256;
        int row = idx >> 3, c8 = idx & 7;
        int gr = rowbase + row;
        if (clampE) gr = (gr < L_) ? gr : (L_ - 1);
        cpa16(sbase + woff + (uint32_t)(row * TSTRIDE + c8 * 16),
              src + (size_t)gr * DH_ + c8 * 8);
    }
}

// acc[8][4] = Qwarp(16 x 64) * tile(64 x 64)^T, plain fp16
__device__ __forceinline__ void gemm_tile(float acc[8][4],
    const uint32_t qf[4][4], uint32_t th, uint32_t boff)
{
    #pragma unroll
    for (int f = 0; f < 8; f++)
        #pragma unroll
        for (int c = 0; c < 4; c++) acc[f][c] = 0.f;
    #pragma unroll
    for (int kc = 0; kc < 4; kc++) {
        #pragma unroll
        for (int nbp = 0; nbp < 4; nbp++) {
            uint32_t bh_[4];
            ldsm4(bh_, th + (uint32_t)(nbp * 16 * TSTRIDE + kc * 32) + boff);
            mma_f16(acc[2 * nbp],     qf[kc], bh_[0], bh_[1]);
            mma_f16(acc[2 * nbp + 1], qf[kc], bh_[2], bh_[3]);
        }
    }
}

__device__ __forceinline__ void store_panel(__half* pan, const float acc[8][4],
                                            int prow, int tq, int slot)
{
    #pragma unroll
    for (int f = 0; f < 8; f++) {
        *(uint32_t*)&pan[prow * PSTRIDE + slot * 64 + 8 * f + 2 * tq] =
            pack2h(acc[f][0], acc[f][1]);
        *(uint32_t*)&pan[(prow + 8) * PSTRIDE + slot * 64 + 8 * f + 2 * tq] =
            pack2h(acc[f][2], acc[f][3]);
    }
}

__global__ __launch_bounds__(256, 2) void attn_kernel()
{
    extern __shared__ char smc[];
    const uint32_t sbase = smem_u32(smc);
    __half* pan = (__half*)smc;

    const int t  = threadIdx.x;
    const int w  = t >> 5;
    const int ln = t & 31;
    const int g  = ln >> 2;
    const int tq = ln & 3;
    const int qt = (int)(gridDim.x - 1) - (int)blockIdx.x;  // heavy first
    const int l0 = qt * 128;
    const int bh = blockIdx.y;

    const size_t hoff = (size_t)bh * L_ * DH_;

    const uint32_t aoff = (uint32_t)((w * 16 + (ln & 15)) * TSTRIDE + (ln >> 4) * 16);
    const uint32_t boff = (uint32_t)(((ln & 7) + ((ln >> 4) << 3)) * TSTRIDE + (((ln >> 3) & 1) << 4));
    const uint32_t voff = (uint32_t)(((ln & 7) + (((ln >> 3) & 1) << 3)) * TSTRIDE + ((ln >> 4) << 4));

    // prologue: Q tile (aliases panel), 128 consecutive E rows -> BUF_EK
    #pragma unroll
    for (int r = 0; r < 4; r++) {
        int idx = t + r * 256;
        int row = idx >> 3, c8 = idx & 7;
        cpa16(sbase + QH_OFF + (uint32_t)(row * TSTRIDE + c8 * 16),
              g_q + hoff + (size_t)(l0 + row) * DH_ + c8 * 8);
    }
    const int eb = L_ - 128 - l0;   // >= 0 always
    #pragma unroll
    for (int r = 0; r < 4; r++) {
        int idx = t + r * 256;
        int row = idx >> 3, c8 = idx & 7;
        cpa16(sbase + BUF_EK + (uint32_t)(row * TSTRIDE + c8 * 16),
              g_e + (size_t)(eb + row) * DH_ + c8 * 8);
    }
    cpa_wait();
    __syncthreads();

    uint32_t qf[4][4];
    #pragma unroll
    for (int kc = 0; kc < 4; kc++)
        ldsm4(qf[kc], sbase + QH_OFF + kc * 32 + aoff);
    __syncthreads();   // Q smem dead; panel ring writable

    const int rt0 = w * 16 + g;
    const int rt1 = rt0 + 8;
    const int ttmax = (l0 + w * 16 + 15) >> 6;   // last live key tile for warp
    float acc[8][4];

    // prologue panels: slot 0 from E rows [eb, eb+64), slot 1 from [eb+64, eb+128)
    gemm_tile(acc, qf, sbase + BUF_EK, boff);
    store_panel(pan, acc, rt0, tq, 0);
    gemm_tile(acc, qf, sbase + BUF_K, boff);
    store_panel(pan, acc, rt0, tq, 1);
    __syncthreads();   // BUF_EK free

    // EK for iter 0: E rows [eb+128, eb+192) + K tile 0
    load_tile64(sbase, BUF_EK, g_e, eb + 128, t, 1);
    load_tile64(sbase, BUF_K, g_k + hoff, 0, t, 0);
    cpa_wait();
    __syncthreads();

    float Oa[8][4] = {};
    float rm0 = -1e30f, rm1 = -1e30f, rl0 = 0.f, rl1 = 0.f;

    const int ntiles = 2 * qt + 2;

    for (int tt = 0; tt < ntiles; tt++) {
        const int m0k = tt * 64;
        const bool active = (tt <= ttmax);

        // a: V(tt) load (overlaps both gemms)
        load_tile64(sbase, BUF_V, g_v + hoff, m0k, t, 0);

        float mn0 = rm0, mn1 = rm1, cr0 = 1.f, cr1 = 1.f;
        if (active) {
            // b: QE panel -> slot (tt+2)&3 (warp-private)
            gemm_tile(acc, qf, sbase + BUF_EK, boff);
            store_panel(pan, acc, rt0, tq, (tt + 2) & 3);
            __syncwarp();

            // c: S = Q K^T; gather + mask; max/corr
            gemm_tile(acc, qf, sbase + BUF_K, boff);

            const int ofs0 = 64 * tt + 127 - rt0 + 2 * tq;
            const int ofs1 = ofs0 - 8;
            const int lim0 = l0 + rt0 - m0k - 2 * tq;
            const int lim1 = lim0 + 8;
            #pragma unroll
            for (int f = 0; f < 8; f++) {
                #pragma unroll
                for (int c = 0; c < 2; c++) {
                    int p0 = (ofs0 + 8 * f + c) & 255;
                    float rel0 = __half2float(pan[rt0 * PSTRIDE + p0]);
                    float sv0  = (acc[f][c] + rel0) * SCL;
                    acc[f][c]  = (8 * f + c <= lim0) ? sv0 : -1e30f;
                    int p1 = (ofs1 + 8 * f + c) & 255;
                    float rel1 = __half2float(pan[rt1 * PSTRIDE + p1]);
                    float sv1  = (acc[f][2 + c] + rel1) * SCL;
                    acc[f][2 + c] = (8 * f + c <= lim1) ? sv1 : -1e30f;
                }
            }

            float mx0 = -1e30f, mx1 = -1e30f;
            #pragma unroll
            for (int f = 0; f < 8; f++) {
                mx0 = fmaxf(mx0, fmaxf(acc[f][0], acc[f][1]));
                mx1 = fmaxf(mx1, fmaxf(acc[f][2], acc[f][3]));
            }
            mx0 = fmaxf(mx0, __shfl_xor_sync(0xffffffffu, mx0, 1));
            mx0 = fmaxf(mx0, __shfl_xor_sync(0xffffffffu, mx0, 2));
            mx1 = fmaxf(mx1, __shfl_xor_sync(0xffffffffu, mx1, 1));
            mx1 = fmaxf(mx1, __shfl_xor_sync(0xffffffffu, mx1, 2));
            mn0 = fmaxf(rm0, mx0); mn1 = fmaxf(rm1, mx1);
            cr0 = fex2(rm0 - mn0); cr1 = fex2(rm1 - mn1);
            rm0 = mn0; rm1 = mn1;
        }

        // d: V ready; BUF_EK consumed by all warps
        cpa_wait();
        __syncthreads();

        // e: next EK load (overlaps PV)
        if (tt + 1 < ntiles) {
            load_tile64(sbase, BUF_EK, g_e, eb + 64 * (tt + 3), t, 1);
            load_tile64(sbase, BUF_K, g_k + hoff, m0k + 64, t, 0);
        }

        if (active) {
            // conditional Oa rescale (skip when max unchanged warp-wide)
            if (!__all_sync(0xffffffffu, (cr0 == 1.f) && (cr1 == 1.f))) {
                #pragma unroll
                for (int f = 0; f < 8; f++) {
                    Oa[f][0] *= cr0; Oa[f][1] *= cr0;
                    Oa[f][2] *= cr1; Oa[f][3] *= cr1;
                }
            }

            // f: P = 2^(S - mn) packed fp16; row sums via ones-MMA; O += P V
            float ls[4] = {0.f, 0.f, 0.f, 0.f};
            #pragma unroll
            for (int kc = 0; kc < 4; kc++) {
                uint32_t pha[4];
                pha[0] = h2ex2(pack2h(acc[2 * kc][0] - mn0,     acc[2 * kc][1] - mn0));
                pha[1] = h2ex2(pack2h(acc[2 * kc][2] - mn1,     acc[2 * kc][3] - mn1));
                pha[2] = h2ex2(pack2h(acc[2 * kc + 1][0] - mn0, acc[2 * kc + 1][1] - mn0));
                pha[3] = h2ex2(pack2h(acc[2 * kc + 1][2] - mn1, acc[2 * kc + 1][3] - mn1));
                mma_f16(ls, pha, ONESH2, ONESH2);
                #pragma unroll
                for (int nb = 0; nb < 4; nb++) {
                    uint32_t vh_[4];
                    ldsm4t(vh_, sbase + BUF_V
                                 + (uint32_t)(kc * 16 * TSTRIDE + nb * 32) + voff);
                    mma_f16(Oa[2 * nb],     pha, vh_[0], vh_[1]);
                    mma_f16(Oa[2 * nb + 1], pha, vh_[2], vh_[3]);
                }
            }
            rl0 = rl0 * cr0 + ls[0];
            rl1 = rl1 * cr1 + ls[2];
        }

        // g: next EK ready; BUF_V consumed
        cpa_wait();
        __syncthreads();
    }

    // epilogue: fp16 output (fc rounds to fp16 anyway)
    float inv0 = 1.0f / rl0, inv1 = 1.0f / rl1;
    __half* op = g_oh + hoff;
    #pragma unroll
    for (int f = 0; f < 8; f++) {
        int col = 8 * f + 2 * tq;
        *(uint32_t*)(op + (size_t)(l0 + rt0) * DH_ + col) =
            pack2h(Oa[f][0] * inv0, Oa[f][1] * inv0);
        *(uint32_t*)(op + (size_t)(l0 + rt1) * DH_ + col) =
            pack2h(Oa[f][2] * inv1, Oa[f][3] * inv1);
    }
}

// ---------------------------------------------------------------------------
extern "C" void kernel_launch(void* const* d_in, const int* in_sizes, int n_in,
                              void* d_out, int out_size)
{
    const float* Q  = (const float*)d_in[0];
    const float* K  = (const float*)d_in[1];
    const float* V  = (const float*)d_in[2];
    // d_in[3] = mask (causal, known analytically) - unused
    const float* Wq = (const float*)d_in[4];
    const float* bq = (const float*)d_in[5];
    const float* Wk = (const float*)d_in[6];
    const float* bk = (const float*)d_in[7];
    const float* Wv = (const float*)d_in[8];
    const float* bv = (const float*)d_in[9];
    const float* Wf = (const float*)d_in[10];
    const float* bf = (const float*)d_in[11];
    const float* E  = (const float*)d_in[12];
    // d_in[13] = H (known constant 8) - unused
    float* out = (float*)d_out;

    (void)in_sizes; (void)n_in; (void)out_size;

    eprep_kernel<<<(L_ * DH_ + 255) / 256, 256>>>(E);
    wprep_kernel<<<(D_ * D_ + 255) / 256, 256>>>(Wq, Wk, Wv, Wf);

    cudaFuncSetAttribute(proj_mma_kernel, cudaFuncAttributeMaxDynamicSharedMemorySize,
                         GEMM_SMEM);
    cudaFuncSetAttribute(fc_mma_kernel, cudaFuncAttributeMaxDynamicSharedMemorySize,
                         GEMM_SMEM);
    cudaFuncSetAttribute(attn_kernel, cudaFuncAttributeMaxDynamicSharedMemorySize,
                         ATTN_SMEM);

    dim3 gproj(NTOK / 128, D_ / 128, 3);
    proj_mma_kernel<<<gproj, 256, GEMM_SMEM>>>(Q, K, V, bq, bk, bv);

    dim3 gattn(L_ / 128, B_ * H_);
    attn_kernel<<<gattn, 256, ATTN_SMEM>>>();

    dim3 gfc(NTOK / 128, D_ / 128);
    fc_mma_kernel<<<gfc, 256, GEMM_SMEM>>>(bf, out);
}